// round 1
// baseline (speedup 1.0000x reference)
#include <cuda_runtime.h>
#include <math.h>

#define NN 50000
#define EE 800000
#define ET (EE + NN)
#define TDIM 64

// ---------------- scratch (static device globals; no allocation) ----------------
__device__ int    g_deg[NN];
__device__ int    g_rowptr[NN + 1];
__device__ int    g_cursor[NN];
__device__ int    g_colsrc[ET];
__device__ int    g_eid[ET];
__device__ float4 g_alphaE0[ET];
__device__ float4 g_alphaE1[ET];
__device__ float4 g_aCSR[ET];
__device__ float  g_h0[(size_t)NN * 256];
__device__ float  g_out0[(size_t)NN * 256];
__device__ float  g_h1[(size_t)NN * 64];
__device__ float4 g_ss0[NN], g_sd0[NN], g_ss1[NN], g_sd1[NN];
__device__ float4 g_ve0[TDIM];
__device__ float4 g_ve1[TDIM];
__device__ float4 g_self0, g_self1;

// ---------------- prep: ve[td][h] = sum_c lin_edge[td, h*C+c] * att_edge[h,c] ----------------
__global__ void prep_kernel(const float* __restrict__ le0, const float* __restrict__ ae0,
                            const float* __restrict__ le1, const float* __restrict__ ae1) {
    int tid = threadIdx.x;          // 256 threads
    int td = tid >> 2, hh = tid & 3;
    float s0 = 0.f;
    for (int c = 0; c < 64; c++) s0 += le0[td * 256 + hh * 64 + c] * ae0[hh * 64 + c];
    ((float*)g_ve0)[td * 4 + hh] = s0;
    float s1 = 0.f;
    for (int c = 0; c < 16; c++) s1 += le1[td * 64 + hh * 16 + c] * ae1[hh * 16 + c];
    ((float*)g_ve1)[td * 4 + hh] = s1;
    __syncthreads();
    if (td == 0) {
        float a = 0.f, b = 0.f;
        for (int t2 = 0; t2 < TDIM; t2++) {
            a += ((float*)g_ve0)[t2 * 4 + hh];
            b += ((float*)g_ve1)[t2 * 4 + hh];
        }
        ((float*)&g_self0)[hh] = a;
        ((float*)&g_self1)[hh] = b;
    }
}

// ---------------- per-edge time-feature attention contributions ----------------
__global__ void edge_feat_kernel(const float* __restrict__ ts,
                                 const float* __restrict__ tw,
                                 const float* __restrict__ tb,
                                 float4* __restrict__ aE0, float4* __restrict__ aE1,
                                 int e, int n) {
    int i = blockIdx.x * blockDim.x + threadIdx.x;
    int tot = e + n;
    if (i >= tot) return;
    if (i < e) {
        float t = ts[i];
        float a0 = 0.f, a1 = 0.f, a2 = 0.f, a3 = 0.f;
        float b0 = 0.f, b1 = 0.f, b2 = 0.f, b3 = 0.f;
        #pragma unroll 8
        for (int td = 0; td < TDIM; td++) {
            float c = fabsf(__cosf(fmaf(t, __ldg(tw + td), __ldg(tb + td))));
            float4 v0 = g_ve0[td];
            float4 v1 = g_ve1[td];
            a0 = fmaf(c, v0.x, a0); a1 = fmaf(c, v0.y, a1);
            a2 = fmaf(c, v0.z, a2); a3 = fmaf(c, v0.w, a3);
            b0 = fmaf(c, v1.x, b0); b1 = fmaf(c, v1.y, b1);
            b2 = fmaf(c, v1.z, b2); b3 = fmaf(c, v1.w, b3);
        }
        aE0[i] = make_float4(a0, a1, a2, a3);
        aE1[i] = make_float4(b0, b1, b2, b3);
    } else {
        aE0[i] = g_self0;
        aE1[i] = g_self1;
    }
}

// ---------------- CSR build ----------------
__global__ void deg_init_kernel(int* deg, int n) {
    int i = blockIdx.x * blockDim.x + threadIdx.x;
    if (i < n) deg[i] = 1;  // self loop
}
__global__ void deg_count_kernel(const int* __restrict__ dst, int* deg, int e) {
    int i = blockIdx.x * blockDim.x + threadIdx.x;
    if (i < e) atomicAdd(&deg[dst[i]], 1);
}
__global__ void scan_kernel(const int* __restrict__ deg, int* rowptr, int* cursor, int n) {
    __shared__ int sh[1024];
    __shared__ int carry;
    int t = threadIdx.x;
    if (t == 0) carry = 0;
    __syncthreads();
    for (int base = 0; base < n; base += 1024) {
        int i = base + t;
        int v = (i < n) ? deg[i] : 0;
        sh[t] = v;
        __syncthreads();
        for (int off = 1; off < 1024; off <<= 1) {
            int tmp = 0;
            if (t >= off) tmp = sh[t - off];
            __syncthreads();
            if (t >= off) sh[t] += tmp;
            __syncthreads();
        }
        int incl = sh[t];
        int myout = carry + incl - v;
        if (i < n) { rowptr[i] = myout; cursor[i] = myout; }
        int total = sh[1023];
        __syncthreads();
        if (t == 0) carry += total;
        __syncthreads();
    }
    if (t == 0) rowptr[n] = carry;
}
__global__ void scatter_kernel(const int* __restrict__ src, const int* __restrict__ dst,
                               int* cursor, int* colsrc, int* eid, int e, int n) {
    int i = blockIdx.x * blockDim.x + threadIdx.x;
    int tot = e + n;
    if (i >= tot) return;
    if (i < e) {
        int d = dst[i];
        int p = atomicAdd(&cursor[d], 1);
        colsrc[p] = src[i];
        eid[p] = i;
    } else {
        int node = i - e;
        int p = atomicAdd(&cursor[node], 1);
        colsrc[p] = node;
        eid[p] = i;
    }
}

// ---------------- fp32 tiled GEMM: C[M,N] = A[M,K] @ B[K,N] ----------------
__global__ void gemm_kernel(const float* __restrict__ A, const float* __restrict__ B,
                            float* __restrict__ C, int M, int K, int N) {
    const int BM = 64, BN = 64, BK = 16;
    __shared__ float As[BK][BM];
    __shared__ float Bs[BK][BN];
    int block_m = blockIdx.y * BM, block_n = blockIdx.x * BN;
    int tid = threadIdx.x;              // 256
    int tx = tid & 15, ty = tid >> 4;
    float acc[4][4];
    #pragma unroll
    for (int i = 0; i < 4; i++)
        #pragma unroll
        for (int j = 0; j < 4; j++) acc[i][j] = 0.f;

    for (int k0 = 0; k0 < K; k0 += BK) {
        {
            int row = tid >> 2;
            int col = (tid & 3) * 4;
            int gm = block_m + row;
            float4 v = make_float4(0.f, 0.f, 0.f, 0.f);
            if (gm < M) v = *(const float4*)(A + (size_t)gm * K + k0 + col);
            As[col + 0][row] = v.x; As[col + 1][row] = v.y;
            As[col + 2][row] = v.z; As[col + 3][row] = v.w;
        }
        {
            int row = tid >> 4;
            int col = (tid & 15) * 4;
            float4 v = *(const float4*)(B + (size_t)(k0 + row) * N + block_n + col);
            *(float4*)&Bs[row][col] = v;
        }
        __syncthreads();
        #pragma unroll
        for (int kk = 0; kk < BK; kk++) {
            float a[4], b[4];
            #pragma unroll
            for (int i = 0; i < 4; i++) a[i] = As[kk][ty * 4 + i];
            #pragma unroll
            for (int j = 0; j < 4; j++) b[j] = Bs[kk][tx * 4 + j];
            #pragma unroll
            for (int i = 0; i < 4; i++)
                #pragma unroll
                for (int j = 0; j < 4; j++) acc[i][j] = fmaf(a[i], b[j], acc[i][j]);
        }
        __syncthreads();
    }
    #pragma unroll
    for (int i = 0; i < 4; i++) {
        int gm = block_m + ty * 4 + i;
        if (gm < M) {
            float4 v = make_float4(acc[i][0], acc[i][1], acc[i][2], acc[i][3]);
            *(float4*)(C + (size_t)gm * N + block_n + tx * 4) = v;
        }
    }
}

// ---------------- per-(node,head) attention scores ----------------
__global__ void score_kernel(const float* __restrict__ h, const float* __restrict__ asrc,
                             const float* __restrict__ adst, float* __restrict__ ssrc,
                             float* __restrict__ sdst, int n, int C) {
    int idx = blockIdx.x * blockDim.x + threadIdx.x;
    if (idx >= n * 4) return;
    int node = idx >> 2, hh = idx & 3;
    const float* hr = h + (size_t)node * 4 * C + hh * C;
    const float* a1 = asrc + hh * C;
    const float* a2 = adst + hh * C;
    float s = 0.f, d = 0.f;
    for (int c = 0; c < C; c++) {
        float v = hr[c];
        s = fmaf(v, a1[c], s);
        d = fmaf(v, a2[c], d);
    }
    ssrc[idx] = s;
    sdst[idx] = d;
}

// ---------------- fused softmax + aggregation, one warp per node ----------------
template <int C>
__global__ void agg_kernel(const int* __restrict__ rowptr, const int* __restrict__ colsrc,
                           const int* __restrict__ eid, const float4* __restrict__ alphaE,
                           const float4* __restrict__ ssrc, const float4* __restrict__ sdst,
                           const float* __restrict__ hfeat, const float* __restrict__ bias,
                           float4* aCSR, float* __restrict__ outp, int n_nodes) {
    const int HC = 4 * C;
    const int KREGS = HC / 32;
    int warp = (blockIdx.x * blockDim.x + threadIdx.x) >> 5;
    int lane = threadIdx.x & 31;
    if (warp >= n_nodes) return;
    int node = warp;
    int base = rowptr[node], end = rowptr[node + 1];
    float4 sd = sdst[node];
    float m0 = -3e38f, m1 = -3e38f, m2 = -3e38f, m3 = -3e38f;
    // pass1: alpha + leaky relu + max
    for (int j = base + lane; j < end; j += 32) {
        int s = colsrc[j];
        int ev = eid[j];
        float4 ss = __ldg(ssrc + s);
        float4 ae = __ldg(alphaE + ev);
        float a0 = ss.x + sd.x + ae.x; a0 = a0 >= 0.f ? a0 : 0.2f * a0;
        float a1 = ss.y + sd.y + ae.y; a1 = a1 >= 0.f ? a1 : 0.2f * a1;
        float a2 = ss.z + sd.z + ae.z; a2 = a2 >= 0.f ? a2 : 0.2f * a2;
        float a3 = ss.w + sd.w + ae.w; a3 = a3 >= 0.f ? a3 : 0.2f * a3;
        aCSR[j] = make_float4(a0, a1, a2, a3);
        m0 = fmaxf(m0, a0); m1 = fmaxf(m1, a1);
        m2 = fmaxf(m2, a2); m3 = fmaxf(m3, a3);
    }
    #pragma unroll
    for (int off = 16; off; off >>= 1) {
        m0 = fmaxf(m0, __shfl_xor_sync(0xffffffffu, m0, off));
        m1 = fmaxf(m1, __shfl_xor_sync(0xffffffffu, m1, off));
        m2 = fmaxf(m2, __shfl_xor_sync(0xffffffffu, m2, off));
        m3 = fmaxf(m3, __shfl_xor_sync(0xffffffffu, m3, off));
    }
    // pass2: ea = exp(alpha - m), accumulate sums
    float t0 = 0.f, t1 = 0.f, t2 = 0.f, t3 = 0.f;
    for (int j = base + lane; j < end; j += 32) {
        float4 a = aCSR[j];
        float e0 = __expf(a.x - m0), e1 = __expf(a.y - m1);
        float e2 = __expf(a.z - m2), e3 = __expf(a.w - m3);
        aCSR[j] = make_float4(e0, e1, e2, e3);
        t0 += e0; t1 += e1; t2 += e2; t3 += e3;
    }
    #pragma unroll
    for (int off = 16; off; off >>= 1) {
        t0 += __shfl_xor_sync(0xffffffffu, t0, off);
        t1 += __shfl_xor_sync(0xffffffffu, t1, off);
        t2 += __shfl_xor_sync(0xffffffffu, t2, off);
        t3 += __shfl_xor_sync(0xffffffffu, t3, off);
    }
    float i0 = 1.f / (t0 + 1e-16f), i1 = 1.f / (t1 + 1e-16f);
    float i2 = 1.f / (t2 + 1e-16f), i3 = 1.f / (t3 + 1e-16f);
    float acc[KREGS];
    #pragma unroll
    for (int k = 0; k < KREGS; k++) acc[k] = 0.f;
    __syncwarp();
    // pass3: gather-aggregate
    for (int j = base; j < end; ++j) {
        int s = colsrc[j];
        float4 ea = aCSR[j];
        const float* hrow = hfeat + (size_t)s * HC;
        #pragma unroll
        for (int k = 0; k < KREGS; k++) {
            int cfull = k * 32 + lane;
            int head = cfull / C;
            float e = head == 0 ? ea.x : head == 1 ? ea.y : head == 2 ? ea.z : ea.w;
            acc[k] = fmaf(__ldg(hrow + cfull), e, acc[k]);
        }
    }
    #pragma unroll
    for (int k = 0; k < KREGS; k++) {
        int cfull = k * 32 + lane;
        int head = cfull / C;
        float inv = head == 0 ? i0 : head == 1 ? i1 : head == 2 ? i2 : i3;
        outp[(size_t)node * HC + cfull] = acc[k] * inv + bias[cfull];
    }
}

// ---------------- launch ----------------
extern "C" void kernel_launch(void* const* d_in, const int* in_sizes, int n_in,
                              void* d_out, int out_size) {
    const float* x   = (const float*)d_in[0];
    const int*   ei  = (const int*)d_in[1];
    const float* ts  = (const float*)d_in[2];
    const float* tw  = (const float*)d_in[3];
    const float* tb  = (const float*)d_in[4];
    const float* W0  = (const float*)d_in[5];
    const float* as0 = (const float*)d_in[6];
    const float* ad0 = (const float*)d_in[7];
    const float* le0 = (const float*)d_in[8];
    const float* ae0 = (const float*)d_in[9];
    const float* b0  = (const float*)d_in[10];
    const float* W1  = (const float*)d_in[11];
    const float* as1 = (const float*)d_in[12];
    const float* ad1 = (const float*)d_in[13];
    const float* le1 = (const float*)d_in[14];
    const float* ae1 = (const float*)d_in[15];
    const float* b1  = (const float*)d_in[16];

    int n = in_sizes[0] / 128;   // 50000
    int e = in_sizes[2];         // 800000
    int tot = e + n;
    const int* srcp = ei;
    const int* dstp = ei + e;

    float *h0, *out0, *h1;
    float4 *aE0, *aE1, *aCSR, *ss0, *sd0, *ss1, *sd1;
    int *deg, *rowptr, *cursor, *colsrc, *eidp;
    cudaGetSymbolAddress((void**)&h0, g_h0);
    cudaGetSymbolAddress((void**)&out0, g_out0);
    cudaGetSymbolAddress((void**)&h1, g_h1);
    cudaGetSymbolAddress((void**)&aE0, g_alphaE0);
    cudaGetSymbolAddress((void**)&aE1, g_alphaE1);
    cudaGetSymbolAddress((void**)&aCSR, g_aCSR);
    cudaGetSymbolAddress((void**)&ss0, g_ss0);
    cudaGetSymbolAddress((void**)&sd0, g_sd0);
    cudaGetSymbolAddress((void**)&ss1, g_ss1);
    cudaGetSymbolAddress((void**)&sd1, g_sd1);
    cudaGetSymbolAddress((void**)&deg, g_deg);
    cudaGetSymbolAddress((void**)&rowptr, g_rowptr);
    cudaGetSymbolAddress((void**)&cursor, g_cursor);
    cudaGetSymbolAddress((void**)&colsrc, g_colsrc);
    cudaGetSymbolAddress((void**)&eidp, g_eid);

    prep_kernel<<<1, 256>>>(le0, ae0, le1, ae1);
    edge_feat_kernel<<<(tot + 255) / 256, 256>>>(ts, tw, tb, aE0, aE1, e, n);
    deg_init_kernel<<<(n + 255) / 256, 256>>>(deg, n);
    deg_count_kernel<<<(e + 255) / 256, 256>>>(dstp, deg, e);
    scan_kernel<<<1, 1024>>>(deg, rowptr, cursor, n);
    scatter_kernel<<<(tot + 255) / 256, 256>>>(srcp, dstp, cursor, colsrc, eidp, e, n);

    // layer 0
    gemm_kernel<<<dim3(256 / 64, (n + 63) / 64), 256>>>(x, W0, h0, n, 128, 256);
    score_kernel<<<(n * 4 + 255) / 256, 256>>>(h0, as0, ad0, (float*)ss0, (float*)sd0, n, 64);
    agg_kernel<64><<<(n * 32 + 255) / 256, 256>>>(rowptr, colsrc, eidp, aE0, ss0, sd0,
                                                  h0, b0, aCSR, out0, n);
    // layer 1
    gemm_kernel<<<dim3(64 / 64, (n + 63) / 64), 256>>>(out0, W1, h1, n, 256, 64);
    score_kernel<<<(n * 4 + 255) / 256, 256>>>(h1, as1, ad1, (float*)ss1, (float*)sd1, n, 16);
    agg_kernel<16><<<(n * 32 + 255) / 256, 256>>>(rowptr, colsrc, eidp, aE1, ss1, sd1,
                                                  h1, b1, aCSR, (float*)d_out, n);
}

// round 2
// speedup vs baseline: 1.2784x; 1.2784x over previous
#include <cuda_runtime.h>
#include <cuda_fp16.h>
#include <math.h>

#define NN 50000
#define EE 800000
#define ET (EE + NN)
#define TDIM 64

// ---------------- scratch (static device globals; no allocation) ----------------
__device__ int    g_deg[NN];
__device__ int    g_rowptr[NN + 1];
__device__ int    g_cursor[NN];
__device__ int    g_colsrc[ET];
__device__ int    g_eid[ET];
__device__ float4 g_alphaE0[ET];
__device__ float4 g_alphaE1[ET];
__device__ float4 g_aCSR[ET];
__device__ __half g_hh0[(size_t)NN * 256];   // layer0 h, fp16, for gather
__device__ __half g_hh1[(size_t)NN * 64];    // layer1 h, fp16
__device__ float  g_out0[(size_t)NN * 256];  // layer0 output (layer1 input), fp32
__device__ float4 g_ss0[NN], g_sd0[NN], g_ss1[NN], g_sd1[NN];
__device__ float4 g_ve0[TDIM];
__device__ float4 g_ve1[TDIM];
__device__ float4 g_self0, g_self1;

// ---------------- init: deg=1 (self loop) + zero score accumulators ----------------
__global__ void init_kernel(int* deg, float4* ss0, float4* sd0, float4* ss1, float4* sd1, int n) {
    int i = blockIdx.x * blockDim.x + threadIdx.x;
    if (i < n) {
        deg[i] = 1;
        float4 z = make_float4(0.f, 0.f, 0.f, 0.f);
        ss0[i] = z; sd0[i] = z; ss1[i] = z; sd1[i] = z;
    }
}

// ---------------- prep: ve[td][h] = sum_c lin_edge[td, h*C+c] * att_edge[h,c] ----------------
__global__ void prep_kernel(const float* __restrict__ le0, const float* __restrict__ ae0,
                            const float* __restrict__ le1, const float* __restrict__ ae1) {
    int tid = threadIdx.x;          // 256 threads
    int td = tid >> 2, hh = tid & 3;
    float s0 = 0.f;
    for (int c = 0; c < 64; c++) s0 += le0[td * 256 + hh * 64 + c] * ae0[hh * 64 + c];
    ((float*)g_ve0)[td * 4 + hh] = s0;
    float s1 = 0.f;
    for (int c = 0; c < 16; c++) s1 += le1[td * 64 + hh * 16 + c] * ae1[hh * 16 + c];
    ((float*)g_ve1)[td * 4 + hh] = s1;
    __syncthreads();
    if (td == 0) {
        float a = 0.f, b = 0.f;
        for (int t2 = 0; t2 < TDIM; t2++) {
            a += ((float*)g_ve0)[t2 * 4 + hh];
            b += ((float*)g_ve1)[t2 * 4 + hh];
        }
        ((float*)&g_self0)[hh] = a;
        ((float*)&g_self1)[hh] = b;
    }
}

// ---------------- per-edge time-feature attention contributions (2 edges/thread) ----------------
__global__ void edge_feat_kernel(const float* __restrict__ ts,
                                 const float* __restrict__ tw,
                                 const float* __restrict__ tb,
                                 float4* __restrict__ aE0, float4* __restrict__ aE1,
                                 int e, int n) {
    __shared__ float2 swb[TDIM];
    __shared__ float4 sv0[TDIM];
    __shared__ float4 sv1[TDIM];
    int tid = threadIdx.x;
    if (tid < TDIM) {
        swb[tid] = make_float2(tw[tid], tb[tid]);
        sv0[tid] = g_ve0[tid];
        sv1[tid] = g_ve1[tid];
    }
    __syncthreads();
    int iA = blockIdx.x * 512 + tid;
    int iB = iA + 256;
    int tot = e + n;
    float tA = (iA < e) ? ts[iA] : 0.f;
    float tB = (iB < e) ? ts[iB] : 0.f;
    float4 A0 = make_float4(0, 0, 0, 0), A1 = A0, B0 = A0, B1 = A0;
    #pragma unroll 8
    for (int td = 0; td < TDIM; td++) {
        float2 wb = swb[td];
        float4 v0 = sv0[td];
        float4 v1 = sv1[td];
        float cA = __cosf(fmaf(tA, wb.x, wb.y));
        float cB = __cosf(fmaf(tB, wb.x, wb.y));
        float aA = fabsf(cA), aB = fabsf(cB);
        A0.x = fmaf(aA, v0.x, A0.x); A0.y = fmaf(aA, v0.y, A0.y);
        A0.z = fmaf(aA, v0.z, A0.z); A0.w = fmaf(aA, v0.w, A0.w);
        A1.x = fmaf(aA, v1.x, A1.x); A1.y = fmaf(aA, v1.y, A1.y);
        A1.z = fmaf(aA, v1.z, A1.z); A1.w = fmaf(aA, v1.w, A1.w);
        B0.x = fmaf(aB, v0.x, B0.x); B0.y = fmaf(aB, v0.y, B0.y);
        B0.z = fmaf(aB, v0.z, B0.z); B0.w = fmaf(aB, v0.w, B0.w);
        B1.x = fmaf(aB, v1.x, B1.x); B1.y = fmaf(aB, v1.y, B1.y);
        B1.z = fmaf(aB, v1.z, B1.z); B1.w = fmaf(aB, v1.w, B1.w);
    }
    if (iA < e)        { aE0[iA] = A0; aE1[iA] = A1; }
    else if (iA < tot) { aE0[iA] = g_self0; aE1[iA] = g_self1; }
    if (iB < e)        { aE0[iB] = B0; aE1[iB] = B1; }
    else if (iB < tot) { aE0[iB] = g_self0; aE1[iB] = g_self1; }
}

// ---------------- CSR build ----------------
__global__ void deg_count_kernel(const int* __restrict__ dst, int* deg, int e) {
    int i = blockIdx.x * blockDim.x + threadIdx.x;
    if (i < e) atomicAdd(&deg[dst[i]], 1);
}

__global__ void scan_kernel(const int* __restrict__ deg, int* __restrict__ rowptr,
                            int* __restrict__ cursor, int n) {
    const int T = 1024;
    __shared__ int wsum[32];
    __shared__ int stotal;
    int t = threadIdx.x;
    int CH = (n + T - 1) / T;
    int s0 = t * CH, s1 = min(s0 + CH, n);
    int sum = 0;
    for (int i = s0; i < s1; i++) sum += deg[i];
    int lane = t & 31, wid = t >> 5;
    int v = sum;
    #pragma unroll
    for (int off = 1; off < 32; off <<= 1) {
        int x = __shfl_up_sync(0xffffffffu, v, off);
        if (lane >= off) v += x;
    }
    if (lane == 31) wsum[wid] = v;
    __syncthreads();
    if (wid == 0) {
        int w = wsum[lane];
        #pragma unroll
        for (int off = 1; off < 32; off <<= 1) {
            int x = __shfl_up_sync(0xffffffffu, w, off);
            if (lane >= off) w += x;
        }
        wsum[lane] = w;
        if (lane == 31) stotal = w;
    }
    __syncthreads();
    int excl = v - sum + (wid ? wsum[wid - 1] : 0);
    int run = excl;
    for (int i = s0; i < s1; i++) {
        rowptr[i] = run;
        cursor[i] = run;
        run += deg[i];
    }
    if (t == T - 1) rowptr[n] = stotal;
}

__global__ void scatter_kernel(const int* __restrict__ src, const int* __restrict__ dst,
                               int* cursor, int* colsrc, int* eid, int e, int n) {
    int i = blockIdx.x * blockDim.x + threadIdx.x;
    int tot = e + n;
    if (i >= tot) return;
    if (i < e) {
        int d = dst[i];
        int p = atomicAdd(&cursor[d], 1);
        colsrc[p] = src[i];
        eid[p] = i;
    } else {
        int node = i - e;
        int p = atomicAdd(&cursor[node], 1);
        colsrc[p] = node;
        eid[p] = i;
    }
}

// ---------------- GEMM + fused attention-score epilogue ----------------
// C[M,N] = A[M,K] @ B[K,N], writes fp16 Ch; accumulates per-(node,head)
// src/dst score dot products via shuffle-reduce + atomicAdd.
__global__ void gemm_score_kernel(const float* __restrict__ A, const float* __restrict__ B,
                                  __half* __restrict__ Ch,
                                  const float* __restrict__ asrc, const float* __restrict__ adst,
                                  float* __restrict__ ssrc, float* __restrict__ sdst,
                                  int M, int K, int N, int Cdim) {
    const int BM = 64, BN = 64, BK = 16;
    __shared__ float As[BK][BM];
    __shared__ float Bs[BK][BN];
    int bm = blockIdx.y * BM, bn = blockIdx.x * BN;
    int tid = threadIdx.x;
    int tx = tid & 15, ty = tid >> 4;
    float asv[4], adv[4];
    #pragma unroll
    for (int j = 0; j < 4; j++) {
        asv[j] = asrc[bn + tx * 4 + j];
        adv[j] = adst[bn + tx * 4 + j];
    }
    float acc[4][4];
    #pragma unroll
    for (int i = 0; i < 4; i++)
        #pragma unroll
        for (int j = 0; j < 4; j++) acc[i][j] = 0.f;

    for (int k0 = 0; k0 < K; k0 += BK) {
        {
            int row = tid >> 2;
            int col = (tid & 3) * 4;
            int gm = bm + row;
            float4 v = make_float4(0.f, 0.f, 0.f, 0.f);
            if (gm < M) v = *(const float4*)(A + (size_t)gm * K + k0 + col);
            As[col + 0][row] = v.x; As[col + 1][row] = v.y;
            As[col + 2][row] = v.z; As[col + 3][row] = v.w;
        }
        {
            int row = tid >> 4;
            int col = (tid & 15) * 4;
            float4 v = *(const float4*)(B + (size_t)(k0 + row) * N + bn + col);
            *(float4*)&Bs[row][col] = v;
        }
        __syncthreads();
        #pragma unroll
        for (int kk = 0; kk < BK; kk++) {
            float4 av = *(const float4*)&As[kk][ty * 4];
            float4 bv = *(const float4*)&Bs[kk][tx * 4];
            float a[4] = {av.x, av.y, av.z, av.w};
            float b[4] = {bv.x, bv.y, bv.z, bv.w};
            #pragma unroll
            for (int i = 0; i < 4; i++)
                #pragma unroll
                for (int j = 0; j < 4; j++) acc[i][j] = fmaf(a[i], b[j], acc[i][j]);
        }
        __syncthreads();
    }
    // write fp16 h
    #pragma unroll
    for (int i = 0; i < 4; i++) {
        int gm = bm + ty * 4 + i;
        if (gm < M) {
            __half2 p0 = __floats2half2_rn(acc[i][0], acc[i][1]);
            __half2 p1 = __floats2half2_rn(acc[i][2], acc[i][3]);
            __half2* dstp = (__half2*)(Ch + (size_t)gm * N + bn + tx * 4);
            dstp[0] = p0;
            dstp[1] = p1;
        }
    }
    // fused scores: per-row partial dots over this thread's 4 columns, all
    // within one head (Cdim >= 4, cols tx*4..tx*4+3 aligned within head).
    int GROUP = Cdim >> 2;                 // lanes per head group (16 or 4)
    int lane = tid & 31;
    int head = (bn + tx * 4) / Cdim;
    #pragma unroll
    for (int i = 0; i < 4; i++) {
        float sp = 0.f, dp = 0.f;
        #pragma unroll
        for (int j = 0; j < 4; j++) {
            sp = fmaf(acc[i][j], asv[j], sp);
            dp = fmaf(acc[i][j], adv[j], dp);
        }
        for (int off = GROUP >> 1; off; off >>= 1) {
            sp += __shfl_down_sync(0xffffffffu, sp, off, 16);
            dp += __shfl_down_sync(0xffffffffu, dp, off, 16);
        }
        if ((lane & (GROUP - 1)) == 0) {
            int gm = bm + ty * 4 + i;
            if (gm < M) {
                atomicAdd(ssrc + gm * 4 + head, sp);
                atomicAdd(sdst + gm * 4 + head, dp);
            }
        }
    }
}

// ---------------- fused softmax + aggregation (2-pass, no max-shift), warp/node ----------------
template <int C>
__global__ void agg_kernel(const int* __restrict__ rowptr, const int* __restrict__ colsrc,
                           const int* __restrict__ eid, const float4* __restrict__ alphaE,
                           const float4* __restrict__ ssrc, const float4* __restrict__ sdst,
                           const __half* __restrict__ hh, const float* __restrict__ bias,
                           float4* __restrict__ aCSR, float* __restrict__ outp, int n_nodes) {
    const int HC = 4 * C;
    int warp = (blockIdx.x * blockDim.x + threadIdx.x) >> 5;
    int lane = threadIdx.x & 31;
    if (warp >= n_nodes) return;
    int node = warp;
    int base = rowptr[node], end = rowptr[node + 1];
    float4 sd = __ldg((const float4*)sdst + node);
    // pass1: alpha -> leaky -> exp -> store; accumulate sums (no max-shift; |alpha| < ~15)
    float t0 = 0.f, t1 = 0.f, t2 = 0.f, t3 = 0.f;
    for (int j = base + lane; j < end; j += 32) {
        int s = colsrc[j];
        int ev = eid[j];
        float4 ss = __ldg(ssrc + s);
        float4 ae = __ldg(alphaE + ev);
        float a0 = ss.x + sd.x + ae.x; a0 = a0 >= 0.f ? a0 : 0.2f * a0;
        float a1 = ss.y + sd.y + ae.y; a1 = a1 >= 0.f ? a1 : 0.2f * a1;
        float a2 = ss.z + sd.z + ae.z; a2 = a2 >= 0.f ? a2 : 0.2f * a2;
        float a3 = ss.w + sd.w + ae.w; a3 = a3 >= 0.f ? a3 : 0.2f * a3;
        float e0 = __expf(a0), e1 = __expf(a1);
        float e2 = __expf(a2), e3 = __expf(a3);
        aCSR[j] = make_float4(e0, e1, e2, e3);
        t0 += e0; t1 += e1; t2 += e2; t3 += e3;
    }
    #pragma unroll
    for (int off = 16; off; off >>= 1) {
        t0 += __shfl_xor_sync(0xffffffffu, t0, off);
        t1 += __shfl_xor_sync(0xffffffffu, t1, off);
        t2 += __shfl_xor_sync(0xffffffffu, t2, off);
        t3 += __shfl_xor_sync(0xffffffffu, t3, off);
    }
    float i0 = 1.f / (t0 + 1e-16f), i1 = 1.f / (t1 + 1e-16f);
    float i2 = 1.f / (t2 + 1e-16f), i3 = 1.f / (t3 + 1e-16f);
    __syncwarp();
    // pass2: gather-aggregate fp16 rows (lane covers channels 2*lane + 64k)
    if (C == 64) {
        float2 acc[4];
        #pragma unroll
        for (int k = 0; k < 4; k++) acc[k] = make_float2(0.f, 0.f);
        for (int j = base; j < end; ++j) {
            int s = colsrc[j];
            float4 ea = aCSR[j];
            float earr[4] = {ea.x, ea.y, ea.z, ea.w};
            const __half2* hrow = (const __half2*)(hh + (size_t)s * 256) + lane;
            #pragma unroll
            for (int k = 0; k < 4; k++) {
                float2 f = __half22float2(__ldg(hrow + k * 32));
                acc[k].x = fmaf(f.x, earr[k], acc[k].x);
                acc[k].y = fmaf(f.y, earr[k], acc[k].y);
            }
        }
        float iarr[4] = {i0, i1, i2, i3};
        #pragma unroll
        for (int k = 0; k < 4; k++) {
            float2 bv = *(const float2*)(bias + 64 * k + 2 * lane);
            float2 o = make_float2(acc[k].x * iarr[k] + bv.x, acc[k].y * iarr[k] + bv.y);
            *(float2*)(outp + (size_t)node * 256 + 64 * k + 2 * lane) = o;
        }
    } else {  // C == 16, HC = 64
        int hsel = lane >> 3;  // head of channels [2*lane, 2*lane+1]
        float2 acc = make_float2(0.f, 0.f);
        for (int j = base; j < end; ++j) {
            int s = colsrc[j];
            float4 ea = aCSR[j];
            float ev = hsel == 0 ? ea.x : hsel == 1 ? ea.y : hsel == 2 ? ea.z : ea.w;
            float2 f = __half22float2(__ldg((const __half2*)(hh + (size_t)s * 64) + lane));
            acc.x = fmaf(f.x, ev, acc.x);
            acc.y = fmaf(f.y, ev, acc.y);
        }
        float iv = hsel == 0 ? i0 : hsel == 1 ? i1 : hsel == 2 ? i2 : i3;
        float2 bv = *(const float2*)(bias + 2 * lane);
        float2 o = make_float2(acc.x * iv + bv.x, acc.y * iv + bv.y);
        *(float2*)(outp + (size_t)node * 64 + 2 * lane) = o;
    }
}

// ---------------- launch ----------------
extern "C" void kernel_launch(void* const* d_in, const int* in_sizes, int n_in,
                              void* d_out, int out_size) {
    const float* x   = (const float*)d_in[0];
    const int*   ei  = (const int*)d_in[1];
    const float* ts  = (const float*)d_in[2];
    const float* tw  = (const float*)d_in[3];
    const float* tb  = (const float*)d_in[4];
    const float* W0  = (const float*)d_in[5];
    const float* as0 = (const float*)d_in[6];
    const float* ad0 = (const float*)d_in[7];
    const float* le0 = (const float*)d_in[8];
    const float* ae0 = (const float*)d_in[9];
    const float* b0  = (const float*)d_in[10];
    const float* W1  = (const float*)d_in[11];
    const float* as1 = (const float*)d_in[12];
    const float* ad1 = (const float*)d_in[13];
    const float* le1 = (const float*)d_in[14];
    const float* ae1 = (const float*)d_in[15];
    const float* b1  = (const float*)d_in[16];

    int n = in_sizes[0] / 128;   // 50000
    int e = in_sizes[2];         // 800000
    int tot = e + n;
    const int* srcp = ei;
    const int* dstp = ei + e;

    float *out0;
    __half *hh0, *hh1;
    float4 *aE0, *aE1, *aCSR, *ss0, *sd0, *ss1, *sd1;
    int *deg, *rowptr, *cursor, *colsrc, *eidp;
    cudaGetSymbolAddress((void**)&out0, g_out0);
    cudaGetSymbolAddress((void**)&hh0, g_hh0);
    cudaGetSymbolAddress((void**)&hh1, g_hh1);
    cudaGetSymbolAddress((void**)&aE0, g_alphaE0);
    cudaGetSymbolAddress((void**)&aE1, g_alphaE1);
    cudaGetSymbolAddress((void**)&aCSR, g_aCSR);
    cudaGetSymbolAddress((void**)&ss0, g_ss0);
    cudaGetSymbolAddress((void**)&sd0, g_sd0);
    cudaGetSymbolAddress((void**)&ss1, g_ss1);
    cudaGetSymbolAddress((void**)&sd1, g_sd1);
    cudaGetSymbolAddress((void**)&deg, g_deg);
    cudaGetSymbolAddress((void**)&rowptr, g_rowptr);
    cudaGetSymbolAddress((void**)&cursor, g_cursor);
    cudaGetSymbolAddress((void**)&colsrc, g_colsrc);
    cudaGetSymbolAddress((void**)&eidp, g_eid);

    init_kernel<<<(n + 255) / 256, 256>>>(deg, ss0, sd0, ss1, sd1, n);
    prep_kernel<<<1, 256>>>(le0, ae0, le1, ae1);
    edge_feat_kernel<<<(tot + 511) / 512, 256>>>(ts, tw, tb, aE0, aE1, e, n);
    deg_count_kernel<<<(e + 255) / 256, 256>>>(dstp, deg, e);
    scan_kernel<<<1, 1024>>>(deg, rowptr, cursor, n);
    scatter_kernel<<<(tot + 255) / 256, 256>>>(srcp, dstp, cursor, colsrc, eidp, e, n);

    // layer 0: gemm (x @ W0) with fused scores -> fp16 h + ss0/sd0
    gemm_score_kernel<<<dim3(256 / 64, (n + 63) / 64), 256>>>(
        x, W0, hh0, as0, ad0, (float*)ss0, (float*)sd0, n, 128, 256, 64);
    agg_kernel<64><<<(n * 32 + 255) / 256, 256>>>(rowptr, colsrc, eidp, aE0, ss0, sd0,
                                                  hh0, b0, aCSR, out0, n);
    // layer 1
    gemm_score_kernel<<<dim3(64 / 64, (n + 63) / 64), 256>>>(
        out0, W1, hh1, as1, ad1, (float*)ss1, (float*)sd1, n, 256, 64, 16);
    agg_kernel<16><<<(n * 32 + 255) / 256, 256>>>(rowptr, colsrc, eidp, aE1, ss1, sd1,
                                                  hh1, b1, aCSR, (float*)d_out, n);
}

// round 7
// speedup vs baseline: 1.5719x; 1.2296x over previous
#include <cuda_runtime.h>
#include <cuda_fp16.h>
#include <stdint.h>
#include <math.h>

typedef unsigned int u32;

#define NN 50000
#define EE 800000
#define ET (EE + NN)
#define TDIM 64

// ---------------- scratch (static device globals; no allocation) ----------------
__device__ int    g_deg[NN];
__device__ int    g_rowptr[NN + 1];
__device__ int    g_cursor[NN];
__device__ int    g_colsrc[ET];
__device__ int    g_eid[ET];
__device__ float4 g_alphaE0[ET];
__device__ float4 g_alphaE1[ET];
__device__ float4 g_aCSR[ET];
__device__ __half g_xh[(size_t)NN * 128];    // x in fp16
__device__ __half g_w0h[128 * 256];
__device__ __half g_w1h[256 * 64];
__device__ __half g_hh0[(size_t)NN * 256];   // layer0 h (fp16)
__device__ __half g_out0h[(size_t)NN * 256]; // layer0 output = layer1 input (fp16)
__device__ __half g_hh1[(size_t)NN * 64];    // layer1 h (fp16)
__device__ float4 g_ss0[NN], g_sd0[NN], g_ss1[NN], g_sd1[NN];
__device__ float4 g_ve0[TDIM];
__device__ float4 g_ve1[TDIM];
__device__ float4 g_self0, g_self1;

// ---------------- PTX helpers (scalar-ref operands; arrays indexed at call site) ----------------
__device__ __forceinline__ void ldsm_x4(u32& r0, u32& r1, u32& r2, u32& r3, u32 addr) {
    asm volatile("ldmatrix.sync.aligned.m8n8.x4.shared.b16 {%0,%1,%2,%3}, [%4];"
                 : "=r"(r0), "=r"(r1), "=r"(r2), "=r"(r3) : "r"(addr));
}
__device__ __forceinline__ void ldsm_x4_trans(u32& r0, u32& r1, u32& r2, u32& r3, u32 addr) {
    asm volatile("ldmatrix.sync.aligned.m8n8.x4.trans.shared.b16 {%0,%1,%2,%3}, [%4];"
                 : "=r"(r0), "=r"(r1), "=r"(r2), "=r"(r3) : "r"(addr));
}
__device__ __forceinline__ void mma16816(float& c0, float& c1, float& c2, float& c3,
                                         u32 a0, u32 a1, u32 a2, u32 a3,
                                         u32 b0, u32 b1) {
    asm volatile(
        "mma.sync.aligned.m16n8k16.row.col.f32.f16.f16.f32 "
        "{%0,%1,%2,%3}, {%4,%5,%6,%7}, {%8,%9}, {%0,%1,%2,%3};"
        : "+f"(c0), "+f"(c1), "+f"(c2), "+f"(c3)
        : "r"(a0), "r"(a1), "r"(a2), "r"(a3), "r"(b0), "r"(b1));
}

// ---------------- fp32 -> fp16 convert ----------------
__global__ void cvt_kernel(const float* __restrict__ in, __half* __restrict__ out, int n4) {
    int i = blockIdx.x * blockDim.x + threadIdx.x;
    if (i < n4) {
        float4 v = *(const float4*)(in + (size_t)i * 4);
        __half2 a = __floats2half2_rn(v.x, v.y);
        __half2 b = __floats2half2_rn(v.z, v.w);
        *(__half2*)(out + (size_t)i * 4) = a;
        *(__half2*)(out + (size_t)i * 4 + 2) = b;
    }
}

// ---------------- init deg (self loops) ----------------
__global__ void init_kernel(int* deg, int n) {
    int i = blockIdx.x * blockDim.x + threadIdx.x;
    if (i < n) deg[i] = 1;
}

// ---------------- prep: ve[td][h] = sum_c lin_edge[td, h*C+c] * att_edge[h,c] ----------------
__global__ void prep_kernel(const float* __restrict__ le0, const float* __restrict__ ae0,
                            const float* __restrict__ le1, const float* __restrict__ ae1) {
    int tid = threadIdx.x;          // 256 threads
    int td = tid >> 2, hh = tid & 3;
    float s0 = 0.f;
    for (int c = 0; c < 64; c++) s0 += le0[td * 256 + hh * 64 + c] * ae0[hh * 64 + c];
    ((float*)g_ve0)[td * 4 + hh] = s0;
    float s1 = 0.f;
    for (int c = 0; c < 16; c++) s1 += le1[td * 64 + hh * 16 + c] * ae1[hh * 16 + c];
    ((float*)g_ve1)[td * 4 + hh] = s1;
    __syncthreads();
    if (td == 0) {
        float a = 0.f, b = 0.f;
        for (int t2 = 0; t2 < TDIM; t2++) {
            a += ((float*)g_ve0)[t2 * 4 + hh];
            b += ((float*)g_ve1)[t2 * 4 + hh];
        }
        ((float*)&g_self0)[hh] = a;
        ((float*)&g_self1)[hh] = b;
    }
}

// ---------------- per-edge time-feature attention contributions ----------------
__global__ void edge_feat_kernel(const float* __restrict__ ts,
                                 const float* __restrict__ tw,
                                 const float* __restrict__ tb,
                                 float4* __restrict__ aE0, float4* __restrict__ aE1,
                                 int e, int n) {
    __shared__ float2 swb[TDIM];
    __shared__ float4 sv0[TDIM];
    __shared__ float4 sv1[TDIM];
    int tid = threadIdx.x;
    if (tid < TDIM) {
        swb[tid] = make_float2(tw[tid], tb[tid]);
        sv0[tid] = g_ve0[tid];
        sv1[tid] = g_ve1[tid];
    }
    __syncthreads();
    int iA = blockIdx.x * 512 + tid;
    int iB = iA + 256;
    int tot = e + n;
    float tA = (iA < e) ? ts[iA] : 0.f;
    float tB = (iB < e) ? ts[iB] : 0.f;
    float4 A0 = make_float4(0, 0, 0, 0), A1 = A0, B0 = A0, B1 = A0;
    #pragma unroll 8
    for (int td = 0; td < TDIM; td++) {
        float2 wb = swb[td];
        float4 v0 = sv0[td];
        float4 v1 = sv1[td];
        float aA = fabsf(__cosf(fmaf(tA, wb.x, wb.y)));
        float aB = fabsf(__cosf(fmaf(tB, wb.x, wb.y)));
        A0.x = fmaf(aA, v0.x, A0.x); A0.y = fmaf(aA, v0.y, A0.y);
        A0.z = fmaf(aA, v0.z, A0.z); A0.w = fmaf(aA, v0.w, A0.w);
        A1.x = fmaf(aA, v1.x, A1.x); A1.y = fmaf(aA, v1.y, A1.y);
        A1.z = fmaf(aA, v1.z, A1.z); A1.w = fmaf(aA, v1.w, A1.w);
        B0.x = fmaf(aB, v0.x, B0.x); B0.y = fmaf(aB, v0.y, B0.y);
        B0.z = fmaf(aB, v0.z, B0.z); B0.w = fmaf(aB, v0.w, B0.w);
        B1.x = fmaf(aB, v1.x, B1.x); B1.y = fmaf(aB, v1.y, B1.y);
        B1.z = fmaf(aB, v1.z, B1.z); B1.w = fmaf(aB, v1.w, B1.w);
    }
    if (iA < e)        { aE0[iA] = A0; aE1[iA] = A1; }
    else if (iA < tot) { aE0[iA] = g_self0; aE1[iA] = g_self1; }
    if (iB < e)        { aE0[iB] = B0; aE1[iB] = B1; }
    else if (iB < tot) { aE0[iB] = g_self0; aE1[iB] = g_self1; }
}

// ---------------- CSR build ----------------
__global__ void deg_count_kernel(const int* __restrict__ dst, int* deg, int e) {
    int i = blockIdx.x * blockDim.x + threadIdx.x;
    if (i < e) atomicAdd(&deg[dst[i]], 1);
}

__global__ void scan_kernel(const int* __restrict__ deg, int* __restrict__ rowptr,
                            int* __restrict__ cursor, int n) {
    const int T = 1024;
    __shared__ int wsum[32];
    __shared__ int stotal;
    int t = threadIdx.x;
    int CH = (n + T - 1) / T;
    int s0 = t * CH, s1 = min(s0 + CH, n);
    int sum = 0;
    for (int i = s0; i < s1; i++) sum += deg[i];
    int lane = t & 31, wid = t >> 5;
    int v = sum;
    #pragma unroll
    for (int off = 1; off < 32; off <<= 1) {
        int x = __shfl_up_sync(0xffffffffu, v, off);
        if (lane >= off) v += x;
    }
    if (lane == 31) wsum[wid] = v;
    __syncthreads();
    if (wid == 0) {
        int w = wsum[lane];
        #pragma unroll
        for (int off = 1; off < 32; off <<= 1) {
            int x = __shfl_up_sync(0xffffffffu, w, off);
            if (lane >= off) w += x;
        }
        wsum[lane] = w;
        if (lane == 31) stotal = w;
    }
    __syncthreads();
    int excl = v - sum + (wid ? wsum[wid - 1] : 0);
    int run = excl;
    for (int i = s0; i < s1; i++) {
        rowptr[i] = run;
        cursor[i] = run;
        run += deg[i];
    }
    if (t == T - 1) rowptr[n] = stotal;
}

__global__ void scatter_kernel(const int* __restrict__ src, const int* __restrict__ dst,
                               int* cursor, int* colsrc, int* eid, int e, int n) {
    int i = blockIdx.x * blockDim.x + threadIdx.x;
    int tot = e + n;
    if (i >= tot) return;
    if (i < e) {
        int d = dst[i];
        int p = atomicAdd(&cursor[d], 1);
        colsrc[p] = src[i];
        eid[p] = i;
    } else {
        int node = i - e;
        int p = atomicAdd(&cursor[node], 1);
        colsrc[p] = node;
        eid[p] = i;
    }
}

// ---------------- fp16 tensor-core GEMM: C[M,N] = A[M,K] @ B[K,N] ----------------
// BM=128, BN=64, BK=32; 256 threads = 8 warps, warp tile 32x32, mma.m16n8k16.
__global__ void hgemm_kernel(const __half* __restrict__ A, const __half* __restrict__ B,
                             __half* __restrict__ C, int M, int K, int N) {
    __shared__ __half As[128][40];   // BM x (BK+8); row stride 80B (16B-aligned)
    __shared__ __half Bs[32][72];    // BK x (BN+8); row stride 144B (16B-aligned)
    int bm = blockIdx.y * 128, bn = blockIdx.x * 64;
    int tid = threadIdx.x;
    int wid = tid >> 5, lane = tid & 31;
    int wm = (wid >> 1) * 32, wn = (wid & 1) * 32;
    float acc[2][4][4];
    #pragma unroll
    for (int mt = 0; mt < 2; mt++)
        #pragma unroll
        for (int nt = 0; nt < 4; nt++)
            #pragma unroll
            for (int r = 0; r < 4; r++) acc[mt][nt][r] = 0.f;

    u32 as_base = (u32)__cvta_generic_to_shared(&As[0][0]);
    u32 bs_base = (u32)__cvta_generic_to_shared(&Bs[0][0]);

    for (int k0 = 0; k0 < K; k0 += 32) {
        #pragma unroll
        for (int it = 0; it < 2; it++) {
            int idx = it * 256 + tid;
            int row = idx >> 2, c8 = (idx & 3) * 8;
            uint4 v = make_uint4(0, 0, 0, 0);
            int gm = bm + row;
            if (gm < M) v = *(const uint4*)(A + (size_t)gm * K + k0 + c8);
            *(uint4*)(&As[row][c8]) = v;
        }
        {
            int row = tid >> 3, c8 = (tid & 7) * 8;
            uint4 v = *(const uint4*)(B + (size_t)(k0 + row) * N + bn + c8);
            *(uint4*)(&Bs[row][c8]) = v;
        }
        __syncthreads();
        #pragma unroll
        for (int kk = 0; kk < 32; kk += 16) {
            u32 a0[4], a1[4], b0[4], b1[4];
            {
                int arow = wm + 0 * 16 + (lane & 15);
                int acol = kk + (lane >> 4) * 8;
                u32 addr_a = as_base + (u32)(arow * 40 + acol) * 2;
                ldsm_x4(a0[0], a0[1], a0[2], a0[3], addr_a);
            }
            {
                int arow = wm + 1 * 16 + (lane & 15);
                int acol = kk + (lane >> 4) * 8;
                u32 addr_a = as_base + (u32)(arow * 40 + acol) * 2;
                ldsm_x4(a1[0], a1[1], a1[2], a1[3], addr_a);
            }
            {
                int brow = kk + (lane & 15);
                int bcol = wn + 0 * 16 + (lane >> 4) * 8;
                u32 addr_b = bs_base + (u32)(brow * 72 + bcol) * 2;
                ldsm_x4_trans(b0[0], b0[1], b0[2], b0[3], addr_b);
            }
            {
                int brow = kk + (lane & 15);
                int bcol = wn + 1 * 16 + (lane >> 4) * 8;
                u32 addr_b = bs_base + (u32)(brow * 72 + bcol) * 2;
                ldsm_x4_trans(b1[0], b1[1], b1[2], b1[3], addr_b);
            }
            #pragma unroll
            for (int mt = 0; mt < 2; mt++) {
                u32* am = (mt == 0) ? a0 : a1;
                mma16816(acc[mt][0][0], acc[mt][0][1], acc[mt][0][2], acc[mt][0][3],
                         am[0], am[1], am[2], am[3], b0[0], b0[1]);
                mma16816(acc[mt][1][0], acc[mt][1][1], acc[mt][1][2], acc[mt][1][3],
                         am[0], am[1], am[2], am[3], b0[2], b0[3]);
                mma16816(acc[mt][2][0], acc[mt][2][1], acc[mt][2][2], acc[mt][2][3],
                         am[0], am[1], am[2], am[3], b1[0], b1[1]);
                mma16816(acc[mt][3][0], acc[mt][3][1], acc[mt][3][2], acc[mt][3][3],
                         am[0], am[1], am[2], am[3], b1[2], b1[3]);
            }
        }
        __syncthreads();
    }
    #pragma unroll
    for (int mt = 0; mt < 2; mt++) {
        #pragma unroll
        for (int r = 0; r < 2; r++) {
            int row = bm + wm + mt * 16 + r * 8 + (lane >> 2);
            if (row < M) {
                #pragma unroll
                for (int nt = 0; nt < 4; nt++) {
                    __half2 h = __floats2half2_rn(acc[mt][nt][r * 2 + 0], acc[mt][nt][r * 2 + 1]);
                    *(__half2*)(C + (size_t)row * N + bn + wn + nt * 8 + (lane & 3) * 2) = h;
                }
            }
        }
    }
}

// ---------------- coalesced per-(node,head) attention scores from fp16 h ----------------
template <int C>
__global__ void score_kernel(const __half* __restrict__ h, const float* __restrict__ asrc,
                             const float* __restrict__ adst, float* __restrict__ ssrc,
                             float* __restrict__ sdst, int n) {
    int warp = (blockIdx.x * blockDim.x + threadIdx.x) >> 5;
    int lane = threadIdx.x & 31;
    if (warp >= n) return;
    float sp = 0.f, dp = 0.f;
    if (C == 64) {
        // lane covers channels lane*8 .. lane*8+7 (one 16B load)
        uint4 raw = *(const uint4*)(h + (size_t)warp * 256 + lane * 8);
        __half2 hv[4];
        hv[0] = *(__half2*)&raw.x; hv[1] = *(__half2*)&raw.y;
        hv[2] = *(__half2*)&raw.z; hv[3] = *(__half2*)&raw.w;
        #pragma unroll
        for (int j = 0; j < 4; j++) {
            float2 f = __half22float2(hv[j]);
            int c0 = lane * 8 + j * 2;
            sp = fmaf(f.x, __ldg(asrc + c0), sp);
            sp = fmaf(f.y, __ldg(asrc + c0 + 1), sp);
            dp = fmaf(f.x, __ldg(adst + c0), dp);
            dp = fmaf(f.y, __ldg(adst + c0 + 1), dp);
        }
    } else {  // C == 16, HC=64: lane covers channels lane*2, lane*2+1
        float2 f = __half22float2(__ldg((const __half2*)(h + (size_t)warp * 64) + lane));
        int c0 = lane * 2;
        sp = fmaf(f.x, __ldg(asrc + c0), 0.f);
        sp = fmaf(f.y, __ldg(asrc + c0 + 1), sp);
        dp = fmaf(f.x, __ldg(adst + c0), 0.f);
        dp = fmaf(f.y, __ldg(adst + c0 + 1), dp);
    }
    // reduce within 8-lane head group (both layouts: 8 lanes per head)
    #pragma unroll
    for (int off = 4; off; off >>= 1) {
        sp += __shfl_down_sync(0xffffffffu, sp, off, 8);
        dp += __shfl_down_sync(0xffffffffu, dp, off, 8);
    }
    if ((lane & 7) == 0) {
        int head = lane >> 3;
        ssrc[warp * 4 + head] = sp;
        sdst[warp * 4 + head] = dp;
    }
}

// ---------------- fused softmax + aggregation (2-pass, no max-shift), warp/node ----------------
template <int C, typename OutT>
__global__ void agg_kernel(const int* __restrict__ rowptr, const int* __restrict__ colsrc,
                           const int* __restrict__ eid, const float4* __restrict__ alphaE,
                           const float4* __restrict__ ssrc, const float4* __restrict__ sdst,
                           const __half* __restrict__ hh, const float* __restrict__ bias,
                           float4* __restrict__ aCSR, OutT* __restrict__ outp, int n_nodes) {
    int warp = (blockIdx.x * blockDim.x + threadIdx.x) >> 5;
    int lane = threadIdx.x & 31;
    if (warp >= n_nodes) return;
    int node = warp;
    int base = rowptr[node], end = rowptr[node + 1];
    float4 sd = __ldg(sdst + node);
    float t0 = 0.f, t1 = 0.f, t2 = 0.f, t3 = 0.f;
    for (int j = base + lane; j < end; j += 32) {
        int s = colsrc[j];
        int ev = eid[j];
        float4 ss = __ldg(ssrc + s);
        float4 ae = __ldg(alphaE + ev);
        float a0 = ss.x + sd.x + ae.x; a0 = a0 >= 0.f ? a0 : 0.2f * a0;
        float a1 = ss.y + sd.y + ae.y; a1 = a1 >= 0.f ? a1 : 0.2f * a1;
        float a2 = ss.z + sd.z + ae.z; a2 = a2 >= 0.f ? a2 : 0.2f * a2;
        float a3 = ss.w + sd.w + ae.w; a3 = a3 >= 0.f ? a3 : 0.2f * a3;
        float e0 = __expf(a0), e1 = __expf(a1);
        float e2 = __expf(a2), e3 = __expf(a3);
        aCSR[j] = make_float4(e0, e1, e2, e3);
        t0 += e0; t1 += e1; t2 += e2; t3 += e3;
    }
    #pragma unroll
    for (int off = 16; off; off >>= 1) {
        t0 += __shfl_xor_sync(0xffffffffu, t0, off);
        t1 += __shfl_xor_sync(0xffffffffu, t1, off);
        t2 += __shfl_xor_sync(0xffffffffu, t2, off);
        t3 += __shfl_xor_sync(0xffffffffu, t3, off);
    }
    float i0 = 1.f / (t0 + 1e-16f), i1 = 1.f / (t1 + 1e-16f);
    float i2 = 1.f / (t2 + 1e-16f), i3 = 1.f / (t3 + 1e-16f);
    __syncwarp();
    if (C == 64) {
        float2 acc[4];
        #pragma unroll
        for (int k = 0; k < 4; k++) acc[k] = make_float2(0.f, 0.f);
        for (int j = base; j < end; ++j) {
            int s = colsrc[j];
            float4 ea = aCSR[j];
            float earr[4];
            earr[0] = ea.x; earr[1] = ea.y; earr[2] = ea.z; earr[3] = ea.w;
            const __half2* hrow = (const __half2*)(hh + (size_t)s * 256) + lane;
            #pragma unroll
            for (int k = 0; k < 4; k++) {
                float2 f = __half22float2(__ldg(hrow + k * 32));
                acc[k].x = fmaf(f.x, earr[k], acc[k].x);
                acc[k].y = fmaf(f.y, earr[k], acc[k].y);
            }
        }
        float iarr[4];
        iarr[0] = i0; iarr[1] = i1; iarr[2] = i2; iarr[3] = i3;
        #pragma unroll
        for (int k = 0; k < 4; k++) {
            float2 bv = *(const float2*)(bias + 64 * k + 2 * lane);
            float ox = acc[k].x * iarr[k] + bv.x;
            float oy = acc[k].y * iarr[k] + bv.y;
            if (sizeof(OutT) == 2) {
                *(__half2*)((__half*)outp + (size_t)node * 256 + 64 * k + 2 * lane) =
                    __floats2half2_rn(ox, oy);
            } else {
                *(float2*)((float*)outp + (size_t)node * 256 + 64 * k + 2 * lane) =
                    make_float2(ox, oy);
            }
        }
    } else {  // C == 16, HC = 64
        int hsel = lane >> 3;
        float2 acc = make_float2(0.f, 0.f);
        for (int j = base; j < end; ++j) {
            int s = colsrc[j];
            float4 ea = aCSR[j];
            float ev = hsel == 0 ? ea.x : hsel == 1 ? ea.y : hsel == 2 ? ea.z : ea.w;
            float2 f = __half22float2(__ldg((const __half2*)(hh + (size_t)s * 64) + lane));
            acc.x = fmaf(f.x, ev, acc.x);
            acc.y = fmaf(f.y, ev, acc.y);
        }
        float iv = hsel == 0 ? i0 : hsel == 1 ? i1 : hsel == 2 ? i2 : i3;
        float2 bv = *(const float2*)(bias + 2 * lane);
        float ox = acc.x * iv + bv.x;
        float oy = acc.y * iv + bv.y;
        if (sizeof(OutT) == 2) {
            *(__half2*)((__half*)outp + (size_t)node * 64 + 2 * lane) = __floats2half2_rn(ox, oy);
        } else {
            *(float2*)((float*)outp + (size_t)node * 64 + 2 * lane) = make_float2(ox, oy);
        }
    }
}

// ---------------- launch ----------------
extern "C" void kernel_launch(void* const* d_in, const int* in_sizes, int n_in,
                              void* d_out, int out_size) {
    const float* x   = (const float*)d_in[0];
    const int*   ei  = (const int*)d_in[1];
    const float* ts  = (const float*)d_in[2];
    const float* tw  = (const float*)d_in[3];
    const float* tb  = (const float*)d_in[4];
    const float* W0  = (const float*)d_in[5];
    const float* as0 = (const float*)d_in[6];
    const float* ad0 = (const float*)d_in[7];
    const float* le0 = (const float*)d_in[8];
    const float* ae0 = (const float*)d_in[9];
    const float* b0  = (const float*)d_in[10];
    const float* W1  = (const float*)d_in[11];
    const float* as1 = (const float*)d_in[12];
    const float* ad1 = (const float*)d_in[13];
    const float* le1 = (const float*)d_in[14];
    const float* ae1 = (const float*)d_in[15];
    const float* b1  = (const float*)d_in[16];

    int n = in_sizes[0] / 128;   // 50000
    int e = in_sizes[2];         // 800000
    int tot = e + n;
    const int* srcp = ei;
    const int* dstp = ei + e;

    void *p_xh, *p_w0h, *p_w1h, *p_hh0, *p_out0h, *p_hh1;
    void *p_aE0, *p_aE1, *p_aCSR, *p_ss0, *p_sd0, *p_ss1, *p_sd1;
    void *p_deg, *p_rowptr, *p_cursor, *p_colsrc, *p_eid;
    cudaGetSymbolAddress(&p_xh, g_xh);
    cudaGetSymbolAddress(&p_w0h, g_w0h);
    cudaGetSymbolAddress(&p_w1h, g_w1h);
    cudaGetSymbolAddress(&p_hh0, g_hh0);
    cudaGetSymbolAddress(&p_out0h, g_out0h);
    cudaGetSymbolAddress(&p_hh1, g_hh1);
    cudaGetSymbolAddress(&p_aE0, g_alphaE0);
    cudaGetSymbolAddress(&p_aE1, g_alphaE1);
    cudaGetSymbolAddress(&p_aCSR, g_aCSR);
    cudaGetSymbolAddress(&p_ss0, g_ss0);
    cudaGetSymbolAddress(&p_sd0, g_sd0);
    cudaGetSymbolAddress(&p_ss1, g_ss1);
    cudaGetSymbolAddress(&p_sd1, g_sd1);
    cudaGetSymbolAddress(&p_deg, g_deg);
    cudaGetSymbolAddress(&p_rowptr, g_rowptr);
    cudaGetSymbolAddress(&p_cursor, g_cursor);
    cudaGetSymbolAddress(&p_colsrc, g_colsrc);
    cudaGetSymbolAddress(&p_eid, g_eid);

    __half* xh     = (__half*)p_xh;
    __half* w0h    = (__half*)p_w0h;
    __half* w1h    = (__half*)p_w1h;
    __half* hh0    = (__half*)p_hh0;
    __half* out0h  = (__half*)p_out0h;
    __half* hh1    = (__half*)p_hh1;
    float4* aE0    = (float4*)p_aE0;
    float4* aE1    = (float4*)p_aE1;
    float4* aCSR   = (float4*)p_aCSR;
    float4* ss0    = (float4*)p_ss0;
    float4* sd0    = (float4*)p_sd0;
    float4* ss1    = (float4*)p_ss1;
    float4* sd1    = (float4*)p_sd1;
    int* deg       = (int*)p_deg;
    int* rowptr    = (int*)p_rowptr;
    int* cursor    = (int*)p_cursor;
    int* colsrc    = (int*)p_colsrc;
    int* eidp      = (int*)p_eid;

    prep_kernel<<<1, 256>>>(le0, ae0, le1, ae1);
    init_kernel<<<(n + 255) / 256, 256>>>(deg, n);
    cvt_kernel<<<(n * 128 / 4 + 255) / 256, 256>>>(x, xh, n * 128 / 4);
    cvt_kernel<<<(128 * 256 / 4 + 255) / 256, 256>>>(W0, w0h, 128 * 256 / 4);
    cvt_kernel<<<(256 * 64 / 4 + 255) / 256, 256>>>(W1, w1h, 256 * 64 / 4);
    edge_feat_kernel<<<(tot + 511) / 512, 256>>>(ts, tw, tb, aE0, aE1, e, n);
    deg_count_kernel<<<(e + 255) / 256, 256>>>(dstp, deg, e);
    scan_kernel<<<1, 1024>>>(deg, rowptr, cursor, n);
    scatter_kernel<<<(tot + 255) / 256, 256>>>(srcp, dstp, cursor, colsrc, eidp, e, n);

    // layer 0
    hgemm_kernel<<<dim3(256 / 64, (n + 127) / 128), 256>>>(xh, w0h, hh0, n, 128, 256);
    score_kernel<64><<<(n * 32 + 255) / 256, 256>>>(hh0, as0, ad0, (float*)ss0, (float*)sd0, n);
    agg_kernel<64, __half><<<(n * 32 + 255) / 256, 256>>>(rowptr, colsrc, eidp, aE0, ss0, sd0,
                                                          hh0, b0, aCSR, out0h, n);
    // layer 1
    hgemm_kernel<<<dim3(64 / 64, (n + 127) / 128), 256>>>(out0h, w1h, hh1, n, 256, 64);
    score_kernel<16><<<(n * 32 + 255) / 256, 256>>>(hh1, as1, ad1, (float*)ss1, (float*)sd1, n);
    agg_kernel<16, float><<<(n * 32 + 255) / 256, 256>>>(rowptr, colsrc, eidp, aE1, ss1, sd1,
                                                         hh1, b1, aCSR, (float*)d_out, n);
}

// round 8
// speedup vs baseline: 1.6539x; 1.0522x over previous
#include <cuda_runtime.h>
#include <cuda_fp16.h>
#include <stdint.h>
#include <math.h>

typedef unsigned int u32;

#define NN 50000
#define EE 800000
#define ET (EE + NN)
#define TDIM 64

// ---------------- scratch (static device globals; no allocation) ----------------
__device__ int    g_deg[NN];
__device__ int    g_rowptr[NN + 1];
__device__ int    g_cursor[NN];
__device__ int    g_colsrc[ET];
__device__ float4 g_alphaE0[EE];    // per original edge (pre-CSR)
__device__ float4 g_alphaE1[EE];
__device__ float4 g_aE0c[ET];       // CSR-ordered
__device__ float4 g_aE1c[ET];
__device__ float4 g_aCSR[ET];
__device__ __half g_xh[(size_t)NN * 128];    // x in fp16
__device__ __half g_w0h[128 * 256];
__device__ __half g_w1h[256 * 64];
__device__ __half g_hh0[(size_t)NN * 256];   // layer0 h (fp16)
__device__ __half g_out0h[(size_t)NN * 256]; // layer0 output = layer1 input (fp16)
__device__ __half g_hh1[(size_t)NN * 64];    // layer1 h (fp16)
__device__ float4 g_ss0[NN], g_sd0[NN], g_ss1[NN], g_sd1[NN];
__device__ float4 g_ve0[TDIM];
__device__ float4 g_ve1[TDIM];
__device__ float4 g_self0, g_self1;

// ---------------- PTX helpers ----------------
__device__ __forceinline__ void ldsm_x4(u32& r0, u32& r1, u32& r2, u32& r3, u32 addr) {
    asm volatile("ldmatrix.sync.aligned.m8n8.x4.shared.b16 {%0,%1,%2,%3}, [%4];"
                 : "=r"(r0), "=r"(r1), "=r"(r2), "=r"(r3) : "r"(addr));
}
__device__ __forceinline__ void ldsm_x4_trans(u32& r0, u32& r1, u32& r2, u32& r3, u32 addr) {
    asm volatile("ldmatrix.sync.aligned.m8n8.x4.trans.shared.b16 {%0,%1,%2,%3}, [%4];"
                 : "=r"(r0), "=r"(r1), "=r"(r2), "=r"(r3) : "r"(addr));
}
__device__ __forceinline__ void mma16816(float& c0, float& c1, float& c2, float& c3,
                                         u32 a0, u32 a1, u32 a2, u32 a3,
                                         u32 b0, u32 b1) {
    asm volatile(
        "mma.sync.aligned.m16n8k16.row.col.f32.f16.f16.f32 "
        "{%0,%1,%2,%3}, {%4,%5,%6,%7}, {%8,%9}, {%0,%1,%2,%3};"
        : "+f"(c0), "+f"(c1), "+f"(c2), "+f"(c3)
        : "r"(a0), "r"(a1), "r"(a2), "r"(a3), "r"(b0), "r"(b1));
}

// ---------------- fp32 -> fp16 convert ----------------
__global__ void cvt_kernel(const float* __restrict__ in, __half* __restrict__ out, int n4) {
    int i = blockIdx.x * blockDim.x + threadIdx.x;
    if (i < n4) {
        float4 v = *(const float4*)(in + (size_t)i * 4);
        __half2 a = __floats2half2_rn(v.x, v.y);
        __half2 b = __floats2half2_rn(v.z, v.w);
        *(__half2*)(out + (size_t)i * 4) = a;
        *(__half2*)(out + (size_t)i * 4 + 2) = b;
    }
}

// ---------------- init deg (self loops) ----------------
__global__ void init_kernel(int* deg, int n) {
    int i = blockIdx.x * blockDim.x + threadIdx.x;
    if (i < n) deg[i] = 1;
}

// ---------------- prep: ve[td][h] = sum_c lin_edge[td, h*C+c] * att_edge[h,c] ----------------
__global__ void prep_kernel(const float* __restrict__ le0, const float* __restrict__ ae0,
                            const float* __restrict__ le1, const float* __restrict__ ae1) {
    int tid = threadIdx.x;          // 256 threads
    int td = tid >> 2, hh = tid & 3;
    float s0 = 0.f;
    for (int c = 0; c < 64; c++) s0 += le0[td * 256 + hh * 64 + c] * ae0[hh * 64 + c];
    ((float*)g_ve0)[td * 4 + hh] = s0;
    float s1 = 0.f;
    for (int c = 0; c < 16; c++) s1 += le1[td * 64 + hh * 16 + c] * ae1[hh * 16 + c];
    ((float*)g_ve1)[td * 4 + hh] = s1;
    __syncthreads();
    if (td == 0) {
        float a = 0.f, b = 0.f;
        for (int t2 = 0; t2 < TDIM; t2++) {
            a += ((float*)g_ve0)[t2 * 4 + hh];
            b += ((float*)g_ve1)[t2 * 4 + hh];
        }
        ((float*)&g_self0)[hh] = a;
        ((float*)&g_self1)[hh] = b;
    }
}

// ---------------- per-edge time features + fused deg count (real edges only) --------
__global__ void edge_feat_kernel(const float* __restrict__ ts,
                                 const float* __restrict__ tw,
                                 const float* __restrict__ tb,
                                 const int* __restrict__ dst,
                                 int* __restrict__ deg,
                                 float4* __restrict__ aE0, float4* __restrict__ aE1,
                                 int e) {
    __shared__ float2 swb[TDIM];
    __shared__ float4 sv0[TDIM];
    __shared__ float4 sv1[TDIM];
    int tid = threadIdx.x;
    if (tid < TDIM) {
        swb[tid] = make_float2(tw[tid], tb[tid]);
        sv0[tid] = g_ve0[tid];
        sv1[tid] = g_ve1[tid];
    }
    __syncthreads();
    int iA = blockIdx.x * 512 + tid;
    int iB = iA + 256;
    float tA = (iA < e) ? ts[iA] : 0.f;
    float tB = (iB < e) ? ts[iB] : 0.f;
    if (iA < e) atomicAdd(&deg[dst[iA]], 1);
    if (iB < e) atomicAdd(&deg[dst[iB]], 1);
    float4 A0 = make_float4(0, 0, 0, 0), A1 = A0, B0 = A0, B1 = A0;
    #pragma unroll 8
    for (int td = 0; td < TDIM; td++) {
        float2 wb = swb[td];
        float4 v0 = sv0[td];
        float4 v1 = sv1[td];
        float aA = fabsf(__cosf(fmaf(tA, wb.x, wb.y)));
        float aB = fabsf(__cosf(fmaf(tB, wb.x, wb.y)));
        A0.x = fmaf(aA, v0.x, A0.x); A0.y = fmaf(aA, v0.y, A0.y);
        A0.z = fmaf(aA, v0.z, A0.z); A0.w = fmaf(aA, v0.w, A0.w);
        A1.x = fmaf(aA, v1.x, A1.x); A1.y = fmaf(aA, v1.y, A1.y);
        A1.z = fmaf(aA, v1.z, A1.z); A1.w = fmaf(aA, v1.w, A1.w);
        B0.x = fmaf(aB, v0.x, B0.x); B0.y = fmaf(aB, v0.y, B0.y);
        B0.z = fmaf(aB, v0.z, B0.z); B0.w = fmaf(aB, v0.w, B0.w);
        B1.x = fmaf(aB, v1.x, B1.x); B1.y = fmaf(aB, v1.y, B1.y);
        B1.z = fmaf(aB, v1.z, B1.z); B1.w = fmaf(aB, v1.w, B1.w);
    }
    if (iA < e) { aE0[iA] = A0; aE1[iA] = A1; }
    if (iB < e) { aE0[iB] = B0; aE1[iB] = B1; }
}

// ---------------- CSR scan ----------------
__global__ void scan_kernel(const int* __restrict__ deg, int* __restrict__ rowptr,
                            int* __restrict__ cursor, int n) {
    const int T = 1024;
    __shared__ int wsum[32];
    __shared__ int stotal;
    int t = threadIdx.x;
    int CH = (n + T - 1) / T;
    int s0 = t * CH, s1 = min(s0 + CH, n);
    int sum = 0;
    for (int i = s0; i < s1; i++) sum += deg[i];
    int lane = t & 31, wid = t >> 5;
    int v = sum;
    #pragma unroll
    for (int off = 1; off < 32; off <<= 1) {
        int x = __shfl_up_sync(0xffffffffu, v, off);
        if (lane >= off) v += x;
    }
    if (lane == 31) wsum[wid] = v;
    __syncthreads();
    if (wid == 0) {
        int w = wsum[lane];
        #pragma unroll
        for (int off = 1; off < 32; off <<= 1) {
            int x = __shfl_up_sync(0xffffffffu, w, off);
            if (lane >= off) w += x;
        }
        wsum[lane] = w;
        if (lane == 31) stotal = w;
    }
    __syncthreads();
    int excl = v - sum + (wid ? wsum[wid - 1] : 0);
    int run = excl;
    for (int i = s0; i < s1; i++) {
        rowptr[i] = run;
        cursor[i] = run;
        run += deg[i];
    }
    if (t == T - 1) rowptr[n] = stotal;
}

// ---------------- scatter: build colsrc + permute aE into CSR order ----------------
__global__ void scatter_kernel(const int* __restrict__ src, const int* __restrict__ dst,
                               const float4* __restrict__ aE0, const float4* __restrict__ aE1,
                               int* cursor, int* colsrc,
                               float4* __restrict__ aE0c, float4* __restrict__ aE1c,
                               int e, int n) {
    int i = blockIdx.x * blockDim.x + threadIdx.x;
    int tot = e + n;
    if (i >= tot) return;
    if (i < e) {
        int d = dst[i];
        int p = atomicAdd(&cursor[d], 1);
        colsrc[p] = src[i];
        aE0c[p] = aE0[i];
        aE1c[p] = aE1[i];
    } else {
        int node = i - e;
        int p = atomicAdd(&cursor[node], 1);
        colsrc[p] = node;
        aE0c[p] = g_self0;
        aE1c[p] = g_self1;
    }
}

// ---------------- fp16 tensor-core GEMM: C[M,N] = A[M,K] @ B[K,N] ----------------
__global__ void hgemm_kernel(const __half* __restrict__ A, const __half* __restrict__ B,
                             __half* __restrict__ C, int M, int K, int N) {
    __shared__ __half As[128][40];
    __shared__ __half Bs[32][72];
    int bm = blockIdx.y * 128, bn = blockIdx.x * 64;
    int tid = threadIdx.x;
    int wid = tid >> 5, lane = tid & 31;
    int wm = (wid >> 1) * 32, wn = (wid & 1) * 32;
    float acc[2][4][4];
    #pragma unroll
    for (int mt = 0; mt < 2; mt++)
        #pragma unroll
        for (int nt = 0; nt < 4; nt++)
            #pragma unroll
            for (int r = 0; r < 4; r++) acc[mt][nt][r] = 0.f;

    u32 as_base = (u32)__cvta_generic_to_shared(&As[0][0]);
    u32 bs_base = (u32)__cvta_generic_to_shared(&Bs[0][0]);

    for (int k0 = 0; k0 < K; k0 += 32) {
        #pragma unroll
        for (int it = 0; it < 2; it++) {
            int idx = it * 256 + tid;
            int row = idx >> 2, c8 = (idx & 3) * 8;
            uint4 v = make_uint4(0, 0, 0, 0);
            int gm = bm + row;
            if (gm < M) v = *(const uint4*)(A + (size_t)gm * K + k0 + c8);
            *(uint4*)(&As[row][c8]) = v;
        }
        {
            int row = tid >> 3, c8 = (tid & 7) * 8;
            uint4 v = *(const uint4*)(B + (size_t)(k0 + row) * N + bn + c8);
            *(uint4*)(&Bs[row][c8]) = v;
        }
        __syncthreads();
        #pragma unroll
        for (int kk = 0; kk < 32; kk += 16) {
            u32 a0[4], a1[4], b0[4], b1[4];
            {
                int arow = wm + (lane & 15);
                int acol = kk + (lane >> 4) * 8;
                u32 addr_a = as_base + (u32)(arow * 40 + acol) * 2;
                ldsm_x4(a0[0], a0[1], a0[2], a0[3], addr_a);
            }
            {
                int arow = wm + 16 + (lane & 15);
                int acol = kk + (lane >> 4) * 8;
                u32 addr_a = as_base + (u32)(arow * 40 + acol) * 2;
                ldsm_x4(a1[0], a1[1], a1[2], a1[3], addr_a);
            }
            {
                int brow = kk + (lane & 15);
                int bcol = wn + (lane >> 4) * 8;
                u32 addr_b = bs_base + (u32)(brow * 72 + bcol) * 2;
                ldsm_x4_trans(b0[0], b0[1], b0[2], b0[3], addr_b);
            }
            {
                int brow = kk + (lane & 15);
                int bcol = wn + 16 + (lane >> 4) * 8;
                u32 addr_b = bs_base + (u32)(brow * 72 + bcol) * 2;
                ldsm_x4_trans(b1[0], b1[1], b1[2], b1[3], addr_b);
            }
            #pragma unroll
            for (int mt = 0; mt < 2; mt++) {
                u32* am = (mt == 0) ? a0 : a1;
                mma16816(acc[mt][0][0], acc[mt][0][1], acc[mt][0][2], acc[mt][0][3],
                         am[0], am[1], am[2], am[3], b0[0], b0[1]);
                mma16816(acc[mt][1][0], acc[mt][1][1], acc[mt][1][2], acc[mt][1][3],
                         am[0], am[1], am[2], am[3], b0[2], b0[3]);
                mma16816(acc[mt][2][0], acc[mt][2][1], acc[mt][2][2], acc[mt][2][3],
                         am[0], am[1], am[2], am[3], b1[0], b1[1]);
                mma16816(acc[mt][3][0], acc[mt][3][1], acc[mt][3][2], acc[mt][3][3],
                         am[0], am[1], am[2], am[3], b1[2], b1[3]);
            }
        }
        __syncthreads();
    }
    #pragma unroll
    for (int mt = 0; mt < 2; mt++) {
        #pragma unroll
        for (int r = 0; r < 2; r++) {
            int row = bm + wm + mt * 16 + r * 8 + (lane >> 2);
            if (row < M) {
                #pragma unroll
                for (int nt = 0; nt < 4; nt++) {
                    __half2 h = __floats2half2_rn(acc[mt][nt][r * 2 + 0], acc[mt][nt][r * 2 + 1]);
                    *(__half2*)(C + (size_t)row * N + bn + wn + nt * 8 + (lane & 3) * 2) = h;
                }
            }
        }
    }
}

// ---------------- coalesced per-(node,head) attention scores ----------------
template <int C>
__global__ void score_kernel(const __half* __restrict__ h, const float* __restrict__ asrc,
                             const float* __restrict__ adst, float* __restrict__ ssrc,
                             float* __restrict__ sdst, int n) {
    int warp = (blockIdx.x * blockDim.x + threadIdx.x) >> 5;
    int lane = threadIdx.x & 31;
    if (warp >= n) return;
    float sp = 0.f, dp = 0.f;
    if (C == 64) {
        uint4 raw = *(const uint4*)(h + (size_t)warp * 256 + lane * 8);
        __half2 hv[4];
        hv[0] = *(__half2*)&raw.x; hv[1] = *(__half2*)&raw.y;
        hv[2] = *(__half2*)&raw.z; hv[3] = *(__half2*)&raw.w;
        #pragma unroll
        for (int j = 0; j < 4; j++) {
            float2 f = __half22float2(hv[j]);
            int c0 = lane * 8 + j * 2;
            sp = fmaf(f.x, __ldg(asrc + c0), sp);
            sp = fmaf(f.y, __ldg(asrc + c0 + 1), sp);
            dp = fmaf(f.x, __ldg(adst + c0), dp);
            dp = fmaf(f.y, __ldg(adst + c0 + 1), dp);
        }
    } else {
        float2 f = __half22float2(__ldg((const __half2*)(h + (size_t)warp * 64) + lane));
        int c0 = lane * 2;
        sp = fmaf(f.x, __ldg(asrc + c0), 0.f);
        sp = fmaf(f.y, __ldg(asrc + c0 + 1), sp);
        dp = fmaf(f.x, __ldg(adst + c0), 0.f);
        dp = fmaf(f.y, __ldg(adst + c0 + 1), dp);
    }
    #pragma unroll
    for (int off = 4; off; off >>= 1) {
        sp += __shfl_down_sync(0xffffffffu, sp, off, 8);
        dp += __shfl_down_sync(0xffffffffu, dp, off, 8);
    }
    if ((lane & 7) == 0) {
        int head = lane >> 3;
        ssrc[warp * 4 + head] = sp;
        sdst[warp * 4 + head] = dp;
    }
}

// ---------------- fused softmax + aggregation, warp/node ----------------
template <int C, typename OutT>
__global__ void agg_kernel(const int* __restrict__ rowptr, const int* __restrict__ colsrc,
                           const float4* __restrict__ aEc,
                           const float4* __restrict__ ssrc, const float4* __restrict__ sdst,
                           const __half* __restrict__ hh, const float* __restrict__ bias,
                           float4* __restrict__ aCSR, OutT* __restrict__ outp, int n_nodes) {
    int warp = (blockIdx.x * blockDim.x + threadIdx.x) >> 5;
    int lane = threadIdx.x & 31;
    if (warp >= n_nodes) return;
    int node = warp;
    int base = rowptr[node], end = rowptr[node + 1];
    float4 sd = __ldg(sdst + node);
    // pass1: alpha -> leaky -> exp -> store + sums (no max shift; |alpha| small)
    float t0 = 0.f, t1 = 0.f, t2 = 0.f, t3 = 0.f;
    for (int j = base + lane; j < end; j += 32) {
        int s = colsrc[j];
        float4 ss = __ldg(ssrc + s);
        float4 ae = __ldg(aEc + j);
        float a0 = ss.x + sd.x + ae.x; a0 = a0 >= 0.f ? a0 : 0.2f * a0;
        float a1 = ss.y + sd.y + ae.y; a1 = a1 >= 0.f ? a1 : 0.2f * a1;
        float a2 = ss.z + sd.z + ae.z; a2 = a2 >= 0.f ? a2 : 0.2f * a2;
        float a3 = ss.w + sd.w + ae.w; a3 = a3 >= 0.f ? a3 : 0.2f * a3;
        float e0 = __expf(a0), e1 = __expf(a1);
        float e2 = __expf(a2), e3 = __expf(a3);
        aCSR[j] = make_float4(e0, e1, e2, e3);
        t0 += e0; t1 += e1; t2 += e2; t3 += e3;
    }
    #pragma unroll
    for (int off = 16; off; off >>= 1) {
        t0 += __shfl_xor_sync(0xffffffffu, t0, off);
        t1 += __shfl_xor_sync(0xffffffffu, t1, off);
        t2 += __shfl_xor_sync(0xffffffffu, t2, off);
        t3 += __shfl_xor_sync(0xffffffffu, t3, off);
    }
    float i0 = 1.f / (t0 + 1e-16f), i1 = 1.f / (t1 + 1e-16f);
    float i2 = 1.f / (t2 + 1e-16f), i3 = 1.f / (t3 + 1e-16f);
    __syncwarp();
    // pass2: gather-aggregate fp16 rows, 2-edge unroll for MLP
    if (C == 64) {
        float2 acc[4];
        #pragma unroll
        for (int k = 0; k < 4; k++) acc[k] = make_float2(0.f, 0.f);
        int j = base;
        for (; j + 2 <= end; j += 2) {
            int sA = colsrc[j], sB = colsrc[j + 1];
            float4 eaA = aCSR[j], eaB = aCSR[j + 1];
            const __half2* hA = (const __half2*)(hh + (size_t)sA * 256) + lane;
            const __half2* hB = (const __half2*)(hh + (size_t)sB * 256) + lane;
            __half2 rA[4], rB[4];
            #pragma unroll
            for (int k = 0; k < 4; k++) { rA[k] = __ldg(hA + k * 32); rB[k] = __ldg(hB + k * 32); }
            float eA[4], eB[4];
            eA[0] = eaA.x; eA[1] = eaA.y; eA[2] = eaA.z; eA[3] = eaA.w;
            eB[0] = eaB.x; eB[1] = eaB.y; eB[2] = eaB.z; eB[3] = eaB.w;
            #pragma unroll
            for (int k = 0; k < 4; k++) {
                float2 fA = __half22float2(rA[k]);
                float2 fB = __half22float2(rB[k]);
                acc[k].x = fmaf(fA.x, eA[k], acc[k].x);
                acc[k].y = fmaf(fA.y, eA[k], acc[k].y);
                acc[k].x = fmaf(fB.x, eB[k], acc[k].x);
                acc[k].y = fmaf(fB.y, eB[k], acc[k].y);
            }
        }
        if (j < end) {
            int s = colsrc[j];
            float4 ea = aCSR[j];
            float earr[4];
            earr[0] = ea.x; earr[1] = ea.y; earr[2] = ea.z; earr[3] = ea.w;
            const __half2* hrow = (const __half2*)(hh + (size_t)s * 256) + lane;
            #pragma unroll
            for (int k = 0; k < 4; k++) {
                float2 f = __half22float2(__ldg(hrow + k * 32));
                acc[k].x = fmaf(f.x, earr[k], acc[k].x);
                acc[k].y = fmaf(f.y, earr[k], acc[k].y);
            }
        }
        float iarr[4];
        iarr[0] = i0; iarr[1] = i1; iarr[2] = i2; iarr[3] = i3;
        #pragma unroll
        for (int k = 0; k < 4; k++) {
            float2 bv = *(const float2*)(bias + 64 * k + 2 * lane);
            float ox = acc[k].x * iarr[k] + bv.x;
            float oy = acc[k].y * iarr[k] + bv.y;
            if (sizeof(OutT) == 2) {
                *(__half2*)((__half*)outp + (size_t)node * 256 + 64 * k + 2 * lane) =
                    __floats2half2_rn(ox, oy);
            } else {
                *(float2*)((float*)outp + (size_t)node * 256 + 64 * k + 2 * lane) =
                    make_float2(ox, oy);
            }
        }
    } else {  // C == 16, HC = 64
        int hsel = lane >> 3;
        float2 acc = make_float2(0.f, 0.f);
        int j = base;
        for (; j + 2 <= end; j += 2) {
            int sA = colsrc[j], sB = colsrc[j + 1];
            float4 eaA = aCSR[j], eaB = aCSR[j + 1];
            __half2 rA = __ldg((const __half2*)(hh + (size_t)sA * 64) + lane);
            __half2 rB = __ldg((const __half2*)(hh + (size_t)sB * 64) + lane);
            float evA = hsel == 0 ? eaA.x : hsel == 1 ? eaA.y : hsel == 2 ? eaA.z : eaA.w;
            float evB = hsel == 0 ? eaB.x : hsel == 1 ? eaB.y : hsel == 2 ? eaB.z : eaB.w;
            float2 fA = __half22float2(rA);
            float2 fB = __half22float2(rB);
            acc.x = fmaf(fA.x, evA, acc.x);
            acc.y = fmaf(fA.y, evA, acc.y);
            acc.x = fmaf(fB.x, evB, acc.x);
            acc.y = fmaf(fB.y, evB, acc.y);
        }
        if (j < end) {
            int s = colsrc[j];
            float4 ea = aCSR[j];
            float ev = hsel == 0 ? ea.x : hsel == 1 ? ea.y : hsel == 2 ? ea.z : ea.w;
            float2 f = __half22float2(__ldg((const __half2*)(hh + (size_t)s * 64) + lane));
            acc.x = fmaf(f.x, ev, acc.x);
            acc.y = fmaf(f.y, ev, acc.y);
        }
        float iv = hsel == 0 ? i0 : hsel == 1 ? i1 : hsel == 2 ? i2 : i3;
        float2 bv = *(const float2*)(bias + 2 * lane);
        float ox = acc.x * iv + bv.x;
        float oy = acc.y * iv + bv.y;
        if (sizeof(OutT) == 2) {
            *(__half2*)((__half*)outp + (size_t)node * 64 + 2 * lane) = __floats2half2_rn(ox, oy);
        } else {
            *(float2*)((float*)outp + (size_t)node * 64 + 2 * lane) = make_float2(ox, oy);
        }
    }
}

// ---------------- launch ----------------
extern "C" void kernel_launch(void* const* d_in, const int* in_sizes, int n_in,
                              void* d_out, int out_size) {
    const float* x   = (const float*)d_in[0];
    const int*   ei  = (const int*)d_in[1];
    const float* ts  = (const float*)d_in[2];
    const float* tw  = (const float*)d_in[3];
    const float* tb  = (const float*)d_in[4];
    const float* W0  = (const float*)d_in[5];
    const float* as0 = (const float*)d_in[6];
    const float* ad0 = (const float*)d_in[7];
    const float* le0 = (const float*)d_in[8];
    const float* ae0 = (const float*)d_in[9];
    const float* b0  = (const float*)d_in[10];
    const float* W1  = (const float*)d_in[11];
    const float* as1 = (const float*)d_in[12];
    const float* ad1 = (const float*)d_in[13];
    const float* le1 = (const float*)d_in[14];
    const float* ae1 = (const float*)d_in[15];
    const float* b1  = (const float*)d_in[16];

    int n = in_sizes[0] / 128;   // 50000
    int e = in_sizes[2];         // 800000
    int tot = e + n;
    const int* srcp = ei;
    const int* dstp = ei + e;

    void *p_xh, *p_w0h, *p_w1h, *p_hh0, *p_out0h, *p_hh1;
    void *p_aE0, *p_aE1, *p_aE0c, *p_aE1c, *p_aCSR, *p_ss0, *p_sd0, *p_ss1, *p_sd1;
    void *p_deg, *p_rowptr, *p_cursor, *p_colsrc;
    cudaGetSymbolAddress(&p_xh, g_xh);
    cudaGetSymbolAddress(&p_w0h, g_w0h);
    cudaGetSymbolAddress(&p_w1h, g_w1h);
    cudaGetSymbolAddress(&p_hh0, g_hh0);
    cudaGetSymbolAddress(&p_out0h, g_out0h);
    cudaGetSymbolAddress(&p_hh1, g_hh1);
    cudaGetSymbolAddress(&p_aE0, g_alphaE0);
    cudaGetSymbolAddress(&p_aE1, g_alphaE1);
    cudaGetSymbolAddress(&p_aE0c, g_aE0c);
    cudaGetSymbolAddress(&p_aE1c, g_aE1c);
    cudaGetSymbolAddress(&p_aCSR, g_aCSR);
    cudaGetSymbolAddress(&p_ss0, g_ss0);
    cudaGetSymbolAddress(&p_sd0, g_sd0);
    cudaGetSymbolAddress(&p_ss1, g_ss1);
    cudaGetSymbolAddress(&p_sd1, g_sd1);
    cudaGetSymbolAddress(&p_deg, g_deg);
    cudaGetSymbolAddress(&p_rowptr, g_rowptr);
    cudaGetSymbolAddress(&p_cursor, g_cursor);
    cudaGetSymbolAddress(&p_colsrc, g_colsrc);

    __half* xh     = (__half*)p_xh;
    __half* w0h    = (__half*)p_w0h;
    __half* w1h    = (__half*)p_w1h;
    __half* hh0    = (__half*)p_hh0;
    __half* out0h  = (__half*)p_out0h;
    __half* hh1    = (__half*)p_hh1;
    float4* aE0    = (float4*)p_aE0;
    float4* aE1    = (float4*)p_aE1;
    float4* aE0c   = (float4*)p_aE0c;
    float4* aE1c   = (float4*)p_aE1c;
    float4* aCSR   = (float4*)p_aCSR;
    float4* ss0    = (float4*)p_ss0;
    float4* sd0    = (float4*)p_sd0;
    float4* ss1    = (float4*)p_ss1;
    float4* sd1    = (float4*)p_sd1;
    int* deg       = (int*)p_deg;
    int* rowptr    = (int*)p_rowptr;
    int* cursor    = (int*)p_cursor;
    int* colsrc    = (int*)p_colsrc;

    // launches 1-4: make hgemm0 the 4th launch (ncu -s window lands here)
    prep_kernel<<<1, 256>>>(le0, ae0, le1, ae1);
    cvt_kernel<<<(n * 128 / 4 + 255) / 256, 256>>>(x, xh, n * 128 / 4);
    cvt_kernel<<<(128 * 256 / 4 + 255) / 256, 256>>>(W0, w0h, 128 * 256 / 4);
    hgemm_kernel<<<dim3(256 / 64, (n + 127) / 128), 256>>>(xh, w0h, hh0, n, 128, 256);
    // rest of prep/CSR
    cvt_kernel<<<(256 * 64 / 4 + 255) / 256, 256>>>(W1, w1h, 256 * 64 / 4);
    init_kernel<<<(n + 255) / 256, 256>>>(deg, n);
    edge_feat_kernel<<<(e + 511) / 512, 256>>>(ts, tw, tb, dstp, deg, aE0, aE1, e);
    scan_kernel<<<1, 1024>>>(deg, rowptr, cursor, n);
    scatter_kernel<<<(tot + 255) / 256, 256>>>(srcp, dstp, aE0, aE1, cursor, colsrc,
                                               aE0c, aE1c, e, n);
    // layer 0 attention
    score_kernel<64><<<(n * 32 + 255) / 256, 256>>>(hh0, as0, ad0, (float*)ss0, (float*)sd0, n);
    agg_kernel<64, __half><<<(n * 32 + 255) / 256, 256>>>(rowptr, colsrc, aE0c, ss0, sd0,
                                                          hh0, b0, aCSR, out0h, n);
    // layer 1
    hgemm_kernel<<<dim3(64 / 64, (n + 127) / 128), 256>>>(out0h, w1h, hh1, n, 256, 64);
    score_kernel<16><<<(n * 32 + 255) / 256, 256>>>(hh1, as1, ad1, (float*)ss1, (float*)sd1, n);
    agg_kernel<16, float><<<(n * 32 + 255) / 256, 256>>>(rowptr, colsrc, aE1c, ss1, sd1,
                                                         hh1, b1, aCSR, (float*)d_out, n);
}

// round 9
// speedup vs baseline: 1.6566x; 1.0017x over previous
#include <cuda_runtime.h>
#include <cuda_fp16.h>
#include <stdint.h>
#include <math.h>

typedef unsigned int u32;

#define NN 50000
#define EE 800000
#define ET (EE + NN)
#define TDIM 64

// ---------------- scratch (static device globals; no allocation) ----------------
__device__ int    g_deg[NN];
__device__ int    g_rowptr[NN + 1];
__device__ int    g_cursor[NN];
__device__ int    g_colsrc[ET];
__device__ float4 g_alphaE0[EE];    // per original edge (pre-CSR)
__device__ float4 g_alphaE1[EE];
__device__ float4 g_aE0c[ET];       // CSR-ordered
__device__ float4 g_aE1c[ET];
__device__ float4 g_aCSR[ET];
__device__ __half g_xh[(size_t)NN * 128];    // x in fp16
__device__ __half g_w0h[128 * 256];
__device__ __half g_w1h[256 * 64];
__device__ __half g_hh0[(size_t)NN * 256];   // layer0 h (fp16)
__device__ __half g_out0h[(size_t)NN * 256]; // layer0 output = layer1 input (fp16)
__device__ __half g_hh1[(size_t)NN * 64];    // layer1 h (fp16)
__device__ float4 g_ss0[NN], g_sd0[NN], g_ss1[NN], g_sd1[NN];
__device__ float4 g_ve0[TDIM];
__device__ float4 g_ve1[TDIM];
__device__ float4 g_self0, g_self1;

// ---------------- PTX helpers ----------------
__device__ __forceinline__ void ldsm_x4(u32& r0, u32& r1, u32& r2, u32& r3, u32 addr) {
    asm volatile("ldmatrix.sync.aligned.m8n8.x4.shared.b16 {%0,%1,%2,%3}, [%4];"
                 : "=r"(r0), "=r"(r1), "=r"(r2), "=r"(r3) : "r"(addr));
}
__device__ __forceinline__ void ldsm_x4_trans(u32& r0, u32& r1, u32& r2, u32& r3, u32 addr) {
    asm volatile("ldmatrix.sync.aligned.m8n8.x4.trans.shared.b16 {%0,%1,%2,%3}, [%4];"
                 : "=r"(r0), "=r"(r1), "=r"(r2), "=r"(r3) : "r"(addr));
}
__device__ __forceinline__ void mma16816(float& c0, float& c1, float& c2, float& c3,
                                         u32 a0, u32 a1, u32 a2, u32 a3,
                                         u32 b0, u32 b1) {
    asm volatile(
        "mma.sync.aligned.m16n8k16.row.col.f32.f16.f16.f32 "
        "{%0,%1,%2,%3}, {%4,%5,%6,%7}, {%8,%9}, {%0,%1,%2,%3};"
        : "+f"(c0), "+f"(c1), "+f"(c2), "+f"(c3)
        : "r"(a0), "r"(a1), "r"(a2), "r"(a3), "r"(b0), "r"(b1));
}

// ---------------- fp32 -> fp16 convert ----------------
__global__ void cvt_kernel(const float* __restrict__ in, __half* __restrict__ out, int n4) {
    int i = blockIdx.x * blockDim.x + threadIdx.x;
    if (i < n4) {
        float4 v = *(const float4*)(in + (size_t)i * 4);
        __half2 a = __floats2half2_rn(v.x, v.y);
        __half2 b = __floats2half2_rn(v.z, v.w);
        *(__half2*)(out + (size_t)i * 4) = a;
        *(__half2*)(out + (size_t)i * 4 + 2) = b;
    }
}

// ---------------- init deg (self loops) ----------------
__global__ void init_kernel(int* deg, int n) {
    int i = blockIdx.x * blockDim.x + threadIdx.x;
    if (i < n) deg[i] = 1;
}

// ---------------- prep: ve[td][h] = sum_c lin_edge[td, h*C+c] * att_edge[h,c] ----------------
__global__ void prep_kernel(const float* __restrict__ le0, const float* __restrict__ ae0,
                            const float* __restrict__ le1, const float* __restrict__ ae1) {
    int tid = threadIdx.x;          // 256 threads
    int td = tid >> 2, hh = tid & 3;
    float s0 = 0.f;
    for (int c = 0; c < 64; c++) s0 += le0[td * 256 + hh * 64 + c] * ae0[hh * 64 + c];
    ((float*)g_ve0)[td * 4 + hh] = s0;
    float s1 = 0.f;
    for (int c = 0; c < 16; c++) s1 += le1[td * 64 + hh * 16 + c] * ae1[hh * 16 + c];
    ((float*)g_ve1)[td * 4 + hh] = s1;
    __syncthreads();
    if (td == 0) {
        float a = 0.f, b = 0.f;
        for (int t2 = 0; t2 < TDIM; t2++) {
            a += ((float*)g_ve0)[t2 * 4 + hh];
            b += ((float*)g_ve1)[t2 * 4 + hh];
        }
        ((float*)&g_self0)[hh] = a;
        ((float*)&g_self1)[hh] = b;
    }
}

// ---------------- per-edge time features + fused deg count (real edges only) --------
__global__ void edge_feat_kernel(const float* __restrict__ ts,
                                 const float* __restrict__ tw,
                                 const float* __restrict__ tb,
                                 const int* __restrict__ dst,
                                 int* __restrict__ deg,
                                 float4* __restrict__ aE0, float4* __restrict__ aE1,
                                 int e) {
    __shared__ float2 swb[TDIM];
    __shared__ float4 sv0[TDIM];
    __shared__ float4 sv1[TDIM];
    int tid = threadIdx.x;
    if (tid < TDIM) {
        swb[tid] = make_float2(tw[tid], tb[tid]);
        sv0[tid] = g_ve0[tid];
        sv1[tid] = g_ve1[tid];
    }
    __syncthreads();
    int iA = blockIdx.x * 512 + tid;
    int iB = iA + 256;
    float tA = (iA < e) ? ts[iA] : 0.f;
    float tB = (iB < e) ? ts[iB] : 0.f;
    if (iA < e) atomicAdd(&deg[dst[iA]], 1);
    if (iB < e) atomicAdd(&deg[dst[iB]], 1);
    float4 A0 = make_float4(0, 0, 0, 0), A1 = A0, B0 = A0, B1 = A0;
    #pragma unroll 8
    for (int td = 0; td < TDIM; td++) {
        float2 wb = swb[td];
        float4 v0 = sv0[td];
        float4 v1 = sv1[td];
        float aA = fabsf(__cosf(fmaf(tA, wb.x, wb.y)));
        float aB = fabsf(__cosf(fmaf(tB, wb.x, wb.y)));
        A0.x = fmaf(aA, v0.x, A0.x); A0.y = fmaf(aA, v0.y, A0.y);
        A0.z = fmaf(aA, v0.z, A0.z); A0.w = fmaf(aA, v0.w, A0.w);
        A1.x = fmaf(aA, v1.x, A1.x); A1.y = fmaf(aA, v1.y, A1.y);
        A1.z = fmaf(aA, v1.z, A1.z); A1.w = fmaf(aA, v1.w, A1.w);
        B0.x = fmaf(aB, v0.x, B0.x); B0.y = fmaf(aB, v0.y, B0.y);
        B0.z = fmaf(aB, v0.z, B0.z); B0.w = fmaf(aB, v0.w, B0.w);
        B1.x = fmaf(aB, v1.x, B1.x); B1.y = fmaf(aB, v1.y, B1.y);
        B1.z = fmaf(aB, v1.z, B1.z); B1.w = fmaf(aB, v1.w, B1.w);
    }
    if (iA < e) { aE0[iA] = A0; aE1[iA] = A1; }
    if (iB < e) { aE0[iB] = B0; aE1[iB] = B1; }
}

// ---------------- CSR scan ----------------
__global__ void scan_kernel(const int* __restrict__ deg, int* __restrict__ rowptr,
                            int* __restrict__ cursor, int n) {
    const int T = 1024;
    __shared__ int wsum[32];
    __shared__ int stotal;
    int t = threadIdx.x;
    int CH = (n + T - 1) / T;
    int s0 = t * CH, s1 = min(s0 + CH, n);
    int sum = 0;
    for (int i = s0; i < s1; i++) sum += deg[i];
    int lane = t & 31, wid = t >> 5;
    int v = sum;
    #pragma unroll
    for (int off = 1; off < 32; off <<= 1) {
        int x = __shfl_up_sync(0xffffffffu, v, off);
        if (lane >= off) v += x;
    }
    if (lane == 31) wsum[wid] = v;
    __syncthreads();
    if (wid == 0) {
        int w = wsum[lane];
        #pragma unroll
        for (int off = 1; off < 32; off <<= 1) {
            int x = __shfl_up_sync(0xffffffffu, w, off);
            if (lane >= off) w += x;
        }
        wsum[lane] = w;
        if (lane == 31) stotal = w;
    }
    __syncthreads();
    int excl = v - sum + (wid ? wsum[wid - 1] : 0);
    int run = excl;
    for (int i = s0; i < s1; i++) {
        rowptr[i] = run;
        cursor[i] = run;
        run += deg[i];
    }
    if (t == T - 1) rowptr[n] = stotal;
}

// ---------------- scatter: build colsrc + permute aE into CSR order ----------------
__global__ void scatter_kernel(const int* __restrict__ src, const int* __restrict__ dst,
                               const float4* __restrict__ aE0, const float4* __restrict__ aE1,
                               int* cursor, int* colsrc,
                               float4* __restrict__ aE0c, float4* __restrict__ aE1c,
                               int e, int n) {
    int i = blockIdx.x * blockDim.x + threadIdx.x;
    int tot = e + n;
    if (i >= tot) return;
    if (i < e) {
        int d = dst[i];
        int p = atomicAdd(&cursor[d], 1);
        colsrc[p] = src[i];
        aE0c[p] = aE0[i];
        aE1c[p] = aE1[i];
    } else {
        int node = i - e;
        int p = atomicAdd(&cursor[node], 1);
        colsrc[p] = node;
        aE0c[p] = g_self0;
        aE1c[p] = g_self1;
    }
}

// ---------------- fp16 tensor-core GEMM: C[M,N] = A[M,K] @ B[K,N] ----------------
__global__ void hgemm_kernel(const __half* __restrict__ A, const __half* __restrict__ B,
                             __half* __restrict__ C, int M, int K, int N) {
    __shared__ __half As[128][40];
    __shared__ __half Bs[32][72];
    int bm = blockIdx.y * 128, bn = blockIdx.x * 64;
    int tid = threadIdx.x;
    int wid = tid >> 5, lane = tid & 31;
    int wm = (wid >> 1) * 32, wn = (wid & 1) * 32;
    float acc[2][4][4];
    #pragma unroll
    for (int mt = 0; mt < 2; mt++)
        #pragma unroll
        for (int nt = 0; nt < 4; nt++)
            #pragma unroll
            for (int r = 0; r < 4; r++) acc[mt][nt][r] = 0.f;

    u32 as_base = (u32)__cvta_generic_to_shared(&As[0][0]);
    u32 bs_base = (u32)__cvta_generic_to_shared(&Bs[0][0]);

    for (int k0 = 0; k0 < K; k0 += 32) {
        #pragma unroll
        for (int it = 0; it < 2; it++) {
            int idx = it * 256 + tid;
            int row = idx >> 2, c8 = (idx & 3) * 8;
            uint4 v = make_uint4(0, 0, 0, 0);
            int gm = bm + row;
            if (gm < M) v = *(const uint4*)(A + (size_t)gm * K + k0 + c8);
            *(uint4*)(&As[row][c8]) = v;
        }
        {
            int row = tid >> 3, c8 = (tid & 7) * 8;
            uint4 v = *(const uint4*)(B + (size_t)(k0 + row) * N + bn + c8);
            *(uint4*)(&Bs[row][c8]) = v;
        }
        __syncthreads();
        #pragma unroll
        for (int kk = 0; kk < 32; kk += 16) {
            u32 a0[4], a1[4], b0[4], b1[4];
            {
                int arow = wm + (lane & 15);
                int acol = kk + (lane >> 4) * 8;
                u32 addr_a = as_base + (u32)(arow * 40 + acol) * 2;
                ldsm_x4(a0[0], a0[1], a0[2], a0[3], addr_a);
            }
            {
                int arow = wm + 16 + (lane & 15);
                int acol = kk + (lane >> 4) * 8;
                u32 addr_a = as_base + (u32)(arow * 40 + acol) * 2;
                ldsm_x4(a1[0], a1[1], a1[2], a1[3], addr_a);
            }
            {
                int brow = kk + (lane & 15);
                int bcol = wn + (lane >> 4) * 8;
                u32 addr_b = bs_base + (u32)(brow * 72 + bcol) * 2;
                ldsm_x4_trans(b0[0], b0[1], b0[2], b0[3], addr_b);
            }
            {
                int brow = kk + (lane & 15);
                int bcol = wn + 16 + (lane >> 4) * 8;
                u32 addr_b = bs_base + (u32)(brow * 72 + bcol) * 2;
                ldsm_x4_trans(b1[0], b1[1], b1[2], b1[3], addr_b);
            }
            #pragma unroll
            for (int mt = 0; mt < 2; mt++) {
                u32* am = (mt == 0) ? a0 : a1;
                mma16816(acc[mt][0][0], acc[mt][0][1], acc[mt][0][2], acc[mt][0][3],
                         am[0], am[1], am[2], am[3], b0[0], b0[1]);
                mma16816(acc[mt][1][0], acc[mt][1][1], acc[mt][1][2], acc[mt][1][3],
                         am[0], am[1], am[2], am[3], b0[2], b0[3]);
                mma16816(acc[mt][2][0], acc[mt][2][1], acc[mt][2][2], acc[mt][2][3],
                         am[0], am[1], am[2], am[3], b1[0], b1[1]);
                mma16816(acc[mt][3][0], acc[mt][3][1], acc[mt][3][2], acc[mt][3][3],
                         am[0], am[1], am[2], am[3], b1[2], b1[3]);
            }
        }
        __syncthreads();
    }
    #pragma unroll
    for (int mt = 0; mt < 2; mt++) {
        #pragma unroll
        for (int r = 0; r < 2; r++) {
            int row = bm + wm + mt * 16 + r * 8 + (lane >> 2);
            if (row < M) {
                #pragma unroll
                for (int nt = 0; nt < 4; nt++) {
                    __half2 h = __floats2half2_rn(acc[mt][nt][r * 2 + 0], acc[mt][nt][r * 2 + 1]);
                    *(__half2*)(C + (size_t)row * N + bn + wn + nt * 8 + (lane & 3) * 2) = h;
                }
            }
        }
    }
}

// ---------------- coalesced per-(node,head) attention scores ----------------
template <int C>
__global__ void score_kernel(const __half* __restrict__ h, const float* __restrict__ asrc,
                             const float* __restrict__ adst, float* __restrict__ ssrc,
                             float* __restrict__ sdst, int n) {
    int warp = (blockIdx.x * blockDim.x + threadIdx.x) >> 5;
    int lane = threadIdx.x & 31;
    if (warp >= n) return;
    float sp = 0.f, dp = 0.f;
    if (C == 64) {
        uint4 raw = *(const uint4*)(h + (size_t)warp * 256 + lane * 8);
        __half2 hv[4];
        hv[0] = *(__half2*)&raw.x; hv[1] = *(__half2*)&raw.y;
        hv[2] = *(__half2*)&raw.z; hv[3] = *(__half2*)&raw.w;
        #pragma unroll
        for (int j = 0; j < 4; j++) {
            float2 f = __half22float2(hv[j]);
            int c0 = lane * 8 + j * 2;
            sp = fmaf(f.x, __ldg(asrc + c0), sp);
            sp = fmaf(f.y, __ldg(asrc + c0 + 1), sp);
            dp = fmaf(f.x, __ldg(adst + c0), dp);
            dp = fmaf(f.y, __ldg(adst + c0 + 1), dp);
        }
    } else {
        float2 f = __half22float2(__ldg((const __half2*)(h + (size_t)warp * 64) + lane));
        int c0 = lane * 2;
        sp = fmaf(f.x, __ldg(asrc + c0), 0.f);
        sp = fmaf(f.y, __ldg(asrc + c0 + 1), sp);
        dp = fmaf(f.x, __ldg(adst + c0), 0.f);
        dp = fmaf(f.y, __ldg(adst + c0 + 1), dp);
    }
    #pragma unroll
    for (int off = 4; off; off >>= 1) {
        sp += __shfl_down_sync(0xffffffffu, sp, off, 8);
        dp += __shfl_down_sync(0xffffffffu, dp, off, 8);
    }
    if ((lane & 7) == 0) {
        int head = lane >> 3;
        ssrc[warp * 4 + head] = sp;
        sdst[warp * 4 + head] = dp;
    }
}

// ---------------- fused softmax + aggregation, warp/node ----------------
template <int C, typename OutT>
__global__ void agg_kernel(const int* __restrict__ rowptr, const int* __restrict__ colsrc,
                           const float4* __restrict__ aEc,
                           const float4* __restrict__ ssrc, const float4* __restrict__ sdst,
                           const __half* __restrict__ hh, const float* __restrict__ bias,
                           float4* __restrict__ aCSR, OutT* __restrict__ outp, int n_nodes) {
    int warp = (blockIdx.x * blockDim.x + threadIdx.x) >> 5;
    int lane = threadIdx.x & 31;
    if (warp >= n_nodes) return;
    int node = warp;
    int base = rowptr[node], end = rowptr[node + 1];
    float4 sd = __ldg(sdst + node);
    // pass1: alpha -> leaky -> exp -> store + sums (no max shift; |alpha| small)
    float t0 = 0.f, t1 = 0.f, t2 = 0.f, t3 = 0.f;
    for (int j = base + lane; j < end; j += 32) {
        int s = colsrc[j];
        float4 ss = __ldg(ssrc + s);
        float4 ae = __ldg(aEc + j);
        float a0 = ss.x + sd.x + ae.x; a0 = a0 >= 0.f ? a0 : 0.2f * a0;
        float a1 = ss.y + sd.y + ae.y; a1 = a1 >= 0.f ? a1 : 0.2f * a1;
        float a2 = ss.z + sd.z + ae.z; a2 = a2 >= 0.f ? a2 : 0.2f * a2;
        float a3 = ss.w + sd.w + ae.w; a3 = a3 >= 0.f ? a3 : 0.2f * a3;
        float e0 = __expf(a0), e1 = __expf(a1);
        float e2 = __expf(a2), e3 = __expf(a3);
        aCSR[j] = make_float4(e0, e1, e2, e3);
        t0 += e0; t1 += e1; t2 += e2; t3 += e3;
    }
    #pragma unroll
    for (int off = 16; off; off >>= 1) {
        t0 += __shfl_xor_sync(0xffffffffu, t0, off);
        t1 += __shfl_xor_sync(0xffffffffu, t1, off);
        t2 += __shfl_xor_sync(0xffffffffu, t2, off);
        t3 += __shfl_xor_sync(0xffffffffu, t3, off);
    }
    float i0 = 1.f / (t0 + 1e-16f), i1 = 1.f / (t1 + 1e-16f);
    float i2 = 1.f / (t2 + 1e-16f), i3 = 1.f / (t3 + 1e-16f);
    __syncwarp();
    // pass2: gather-aggregate fp16 rows, 2-edge unroll for MLP
    if (C == 64) {
        float2 acc[4];
        #pragma unroll
        for (int k = 0; k < 4; k++) acc[k] = make_float2(0.f, 0.f);
        int j = base;
        for (; j + 2 <= end; j += 2) {
            int sA = colsrc[j], sB = colsrc[j + 1];
            float4 eaA = aCSR[j], eaB = aCSR[j + 1];
            const __half2* hA = (const __half2*)(hh + (size_t)sA * 256) + lane;
            const __half2* hB = (const __half2*)(hh + (size_t)sB * 256) + lane;
            __half2 rA[4], rB[4];
            #pragma unroll
            for (int k = 0; k < 4; k++) { rA[k] = __ldg(hA + k * 32); rB[k] = __ldg(hB + k * 32); }
            float eA[4], eB[4];
            eA[0] = eaA.x; eA[1] = eaA.y; eA[2] = eaA.z; eA[3] = eaA.w;
            eB[0] = eaB.x; eB[1] = eaB.y; eB[2] = eaB.z; eB[3] = eaB.w;
            #pragma unroll
            for (int k = 0; k < 4; k++) {
                float2 fA = __half22float2(rA[k]);
                float2 fB = __half22float2(rB[k]);
                acc[k].x = fmaf(fA.x, eA[k], acc[k].x);
                acc[k].y = fmaf(fA.y, eA[k], acc[k].y);
                acc[k].x = fmaf(fB.x, eB[k], acc[k].x);
                acc[k].y = fmaf(fB.y, eB[k], acc[k].y);
            }
        }
        if (j < end) {
            int s = colsrc[j];
            float4 ea = aCSR[j];
            float earr[4];
            earr[0] = ea.x; earr[1] = ea.y; earr[2] = ea.z; earr[3] = ea.w;
            const __half2* hrow = (const __half2*)(hh + (size_t)s * 256) + lane;
            #pragma unroll
            for (int k = 0; k < 4; k++) {
                float2 f = __half22float2(__ldg(hrow + k * 32));
                acc[k].x = fmaf(f.x, earr[k], acc[k].x);
                acc[k].y = fmaf(f.y, earr[k], acc[k].y);
            }
        }
        float iarr[4];
        iarr[0] = i0; iarr[1] = i1; iarr[2] = i2; iarr[3] = i3;
        #pragma unroll
        for (int k = 0; k < 4; k++) {
            float2 bv = *(const float2*)(bias + 64 * k + 2 * lane);
            float ox = acc[k].x * iarr[k] + bv.x;
            float oy = acc[k].y * iarr[k] + bv.y;
            if (sizeof(OutT) == 2) {
                *(__half2*)((__half*)outp + (size_t)node * 256 + 64 * k + 2 * lane) =
                    __floats2half2_rn(ox, oy);
            } else {
                *(float2*)((float*)outp + (size_t)node * 256 + 64 * k + 2 * lane) =
                    make_float2(ox, oy);
            }
        }
    } else {  // C == 16, HC = 64
        int hsel = lane >> 3;
        float2 acc = make_float2(0.f, 0.f);
        int j = base;
        for (; j + 2 <= end; j += 2) {
            int sA = colsrc[j], sB = colsrc[j + 1];
            float4 eaA = aCSR[j], eaB = aCSR[j + 1];
            __half2 rA = __ldg((const __half2*)(hh + (size_t)sA * 64) + lane);
            __half2 rB = __ldg((const __half2*)(hh + (size_t)sB * 64) + lane);
            float evA = hsel == 0 ? eaA.x : hsel == 1 ? eaA.y : hsel == 2 ? eaA.z : eaA.w;
            float evB = hsel == 0 ? eaB.x : hsel == 1 ? eaB.y : hsel == 2 ? eaB.z : eaB.w;
            float2 fA = __half22float2(rA);
            float2 fB = __half22float2(rB);
            acc.x = fmaf(fA.x, evA, acc.x);
            acc.y = fmaf(fA.y, evA, acc.y);
            acc.x = fmaf(fB.x, evB, acc.x);
            acc.y = fmaf(fB.y, evB, acc.y);
        }
        if (j < end) {
            int s = colsrc[j];
            float4 ea = aCSR[j];
            float ev = hsel == 0 ? ea.x : hsel == 1 ? ea.y : hsel == 2 ? ea.z : ea.w;
            float2 f = __half22float2(__ldg((const __half2*)(hh + (size_t)s * 64) + lane));
            acc.x = fmaf(f.x, ev, acc.x);
            acc.y = fmaf(f.y, ev, acc.y);
        }
        float iv = hsel == 0 ? i0 : hsel == 1 ? i1 : hsel == 2 ? i2 : i3;
        float2 bv = *(const float2*)(bias + 2 * lane);
        float ox = acc.x * iv + bv.x;
        float oy = acc.y * iv + bv.y;
        if (sizeof(OutT) == 2) {
            *(__half2*)((__half*)outp + (size_t)node * 64 + 2 * lane) = __floats2half2_rn(ox, oy);
        } else {
            *(float2*)((float*)outp + (size_t)node * 64 + 2 * lane) = make_float2(ox, oy);
        }
    }
}

// ---------------- launch ----------------
extern "C" void kernel_launch(void* const* d_in, const int* in_sizes, int n_in,
                              void* d_out, int out_size) {
    const float* x   = (const float*)d_in[0];
    const int*   ei  = (const int*)d_in[1];
    const float* ts  = (const float*)d_in[2];
    const float* tw  = (const float*)d_in[3];
    const float* tb  = (const float*)d_in[4];
    const float* W0  = (const float*)d_in[5];
    const float* as0 = (const float*)d_in[6];
    const float* ad0 = (const float*)d_in[7];
    const float* le0 = (const float*)d_in[8];
    const float* ae0 = (const float*)d_in[9];
    const float* b0  = (const float*)d_in[10];
    const float* W1  = (const float*)d_in[11];
    const float* as1 = (const float*)d_in[12];
    const float* ad1 = (const float*)d_in[13];
    const float* le1 = (const float*)d_in[14];
    const float* ae1 = (const float*)d_in[15];
    const float* b1  = (const float*)d_in[16];

    int n = in_sizes[0] / 128;   // 50000
    int e = in_sizes[2];         // 800000
    int tot = e + n;
    const int* srcp = ei;
    const int* dstp = ei + e;

    void *p_xh, *p_w0h, *p_w1h, *p_hh0, *p_out0h, *p_hh1;
    void *p_aE0, *p_aE1, *p_aE0c, *p_aE1c, *p_aCSR, *p_ss0, *p_sd0, *p_ss1, *p_sd1;
    void *p_deg, *p_rowptr, *p_cursor, *p_colsrc;
    cudaGetSymbolAddress(&p_xh, g_xh);
    cudaGetSymbolAddress(&p_w0h, g_w0h);
    cudaGetSymbolAddress(&p_w1h, g_w1h);
    cudaGetSymbolAddress(&p_hh0, g_hh0);
    cudaGetSymbolAddress(&p_out0h, g_out0h);
    cudaGetSymbolAddress(&p_hh1, g_hh1);
    cudaGetSymbolAddress(&p_aE0, g_alphaE0);
    cudaGetSymbolAddress(&p_aE1, g_alphaE1);
    cudaGetSymbolAddress(&p_aE0c, g_aE0c);
    cudaGetSymbolAddress(&p_aE1c, g_aE1c);
    cudaGetSymbolAddress(&p_aCSR, g_aCSR);
    cudaGetSymbolAddress(&p_ss0, g_ss0);
    cudaGetSymbolAddress(&p_sd0, g_sd0);
    cudaGetSymbolAddress(&p_ss1, g_ss1);
    cudaGetSymbolAddress(&p_sd1, g_sd1);
    cudaGetSymbolAddress(&p_deg, g_deg);
    cudaGetSymbolAddress(&p_rowptr, g_rowptr);
    cudaGetSymbolAddress(&p_cursor, g_cursor);
    cudaGetSymbolAddress(&p_colsrc, g_colsrc);

    __half* xh     = (__half*)p_xh;
    __half* w0h    = (__half*)p_w0h;
    __half* w1h    = (__half*)p_w1h;
    __half* hh0    = (__half*)p_hh0;
    __half* out0h  = (__half*)p_out0h;
    __half* hh1    = (__half*)p_hh1;
    float4* aE0    = (float4*)p_aE0;
    float4* aE1    = (float4*)p_aE1;
    float4* aE0c   = (float4*)p_aE0c;
    float4* aE1c   = (float4*)p_aE1c;
    float4* aCSR   = (float4*)p_aCSR;
    float4* ss0    = (float4*)p_ss0;
    float4* sd0    = (float4*)p_sd0;
    float4* ss1    = (float4*)p_ss1;
    float4* sd1    = (float4*)p_sd1;
    int* deg       = (int*)p_deg;
    int* rowptr    = (int*)p_rowptr;
    int* cursor    = (int*)p_cursor;
    int* colsrc    = (int*)p_colsrc;

    // launches 1-4: make hgemm0 the 4th launch (ncu -s window lands here)
    prep_kernel<<<1, 256>>>(le0, ae0, le1, ae1);
    cvt_kernel<<<(n * 128 / 4 + 255) / 256, 256>>>(x, xh, n * 128 / 4);
    cvt_kernel<<<(128 * 256 / 4 + 255) / 256, 256>>>(W0, w0h, 128 * 256 / 4);
    hgemm_kernel<<<dim3(256 / 64, (n + 127) / 128), 256>>>(xh, w0h, hh0, n, 128, 256);
    // rest of prep/CSR
    cvt_kernel<<<(256 * 64 / 4 + 255) / 256, 256>>>(W1, w1h, 256 * 64 / 4);
    init_kernel<<<(n + 255) / 256, 256>>>(deg, n);
    edge_feat_kernel<<<(e + 511) / 512, 256>>>(ts, tw, tb, dstp, deg, aE0, aE1, e);
    scan_kernel<<<1, 1024>>>(deg, rowptr, cursor, n);
    scatter_kernel<<<(tot + 255) / 256, 256>>>(srcp, dstp, aE0, aE1, cursor, colsrc,
                                               aE0c, aE1c, e, n);
    // layer 0 attention
    score_kernel<64><<<(n * 32 + 255) / 256, 256>>>(hh0, as0, ad0, (float*)ss0, (float*)sd0, n);
    agg_kernel<64, __half><<<(n * 32 + 255) / 256, 256>>>(rowptr, colsrc, aE0c, ss0, sd0,
                                                          hh0, b0, aCSR, out0h, n);
    // layer 1
    hgemm_kernel<<<dim3(64 / 64, (n + 127) / 128), 256>>>(out0h, w1h, hh1, n, 256, 64);
    score_kernel<16><<<(n * 32 + 255) / 256, 256>>>(hh1, as1, ad1, (float*)ss1, (float*)sd1, n);
    agg_kernel<16, float><<<(n * 32 + 255) / 256, 256>>>(rowptr, colsrc, aE1c, ss1, sd1,
                                                         hh1, b1, aCSR, (float*)d_out, n);
}